// round 1
// baseline (speedup 1.0000x reference)
#include <cuda_runtime.h>
#include <cstdint>

#define NN 50000
#define EE 800000
#define CC 128
#define LL 3
#define KK 10

// ---------------- scratch (static __device__ allocations only) ----------------
__device__ __align__(16) float g_h[NN * CC];                 // 25.6 MB
__device__ __align__(16) float g_T[(size_t)NN * 4 * CC];     // 102.4 MB: [hf_i|hf_j|hs_i|hs_j]
__device__ __align__(16) float g_WcatT[LL * CC * 4 * CC];    // [l][k][512]
__device__ __align__(16) float g_AfT[LL * 6 * CC];           // [l][k6][c]
__device__ __align__(16) float g_AsT[LL * 6 * CC];
__device__ __align__(16) float g_cf[LL * CC];
__device__ __align__(16) float g_cs[LL * CC];
__device__ int   g_deg[NN + 1];
__device__ int   g_off[NN + 1];
__device__ int   g_cur[NN];
__device__ int   g_srcs[EE];
__device__ __align__(16) float g_eas[(size_t)EE * 6];
__device__ int   g_is64;

// ---------------- helpers ----------------
__device__ __forceinline__ int load_idx(const void* ei, long long pos) {
    if (g_is64) return (int)(((const long long*)ei)[pos]);
    return ((const int*)ei)[pos];
}

__device__ __forceinline__ float sigf(float z) {
    return __fdividef(1.f, 1.f + __expf(-z));
}
__device__ __forceinline__ float spf(float z) {
    // stable softplus: max(z,0) + log(1+exp(-|z|))
    return fmaxf(z, 0.f) + __logf(1.f + __expf(-fabsf(z)));
}

// ---------------- detect int32 vs int64 edge_index ----------------
__global__ void k_detect(const int* __restrict__ ei32) {
    __shared__ int any;
    if (threadIdx.x == 0) any = 0;
    __syncthreads();
    for (int i = threadIdx.x; i < 4096; i += blockDim.x) {
        if (ei32[2 * i + 1] != 0) any = 1;
    }
    __syncthreads();
    if (threadIdx.x == 0) g_is64 = (any == 0) ? 1 : 0;
}

// ---------------- zero degree histogram ----------------
__global__ void k_zero_deg() {
    int i = blockIdx.x * blockDim.x + threadIdx.x;
    if (i <= NN) g_deg[i] = 0;
}

// ---------------- node encoder: h = x @ node_W.T + node_b ----------------
__global__ void k_node_encode(const float* __restrict__ x,
                              const float* __restrict__ W,
                              const float* __restrict__ b) {
    int i = blockIdx.x * blockDim.x + threadIdx.x;
    if (i >= NN * CC) return;
    int n = i / CC, c = i % CC;
    const float* xr = x + (size_t)n * 7;
    const float* wr = W + (size_t)c * 7;
    float acc = b[c];
#pragma unroll
    for (int k = 0; k < 7; k++) acc = fmaf(xr[k], wr[k], acc);
    g_h[i] = acc;
}

// ---------------- fold edge encoder into layer weights ----------------
// Afe = Wfe @ edge_W  [C,6] (stored transposed k-major), cfe = Wfe @ edge_b + bf
__global__ void k_fold(const float* __restrict__ Wf, const float* __restrict__ bf,
                       const float* __restrict__ Ws, const float* __restrict__ bs,
                       const float* __restrict__ eW, const float* __restrict__ eb) {
    int t = blockIdx.x * blockDim.x + threadIdx.x;
    if (t >= LL * CC * 14) return;
    int l = t / (CC * 14);
    int r = t % (CC * 14);
    int c = r / 14;
    int kk = r % 14;
    const float* rf = Wf + ((size_t)(l * CC + c) * 3 * CC) + 2 * CC;
    const float* rs = Ws + ((size_t)(l * CC + c) * 3 * CC) + 2 * CC;
    if (kk < 6) {
        float s = 0.f;
        for (int j = 0; j < CC; j++) s = fmaf(rf[j], eW[j * 6 + kk], s);
        g_AfT[l * 6 * CC + kk * CC + c] = s;
    } else if (kk < 12) {
        int k = kk - 6;
        float s = 0.f;
        for (int j = 0; j < CC; j++) s = fmaf(rs[j], eW[j * 6 + k], s);
        g_AsT[l * 6 * CC + k * CC + c] = s;
    } else if (kk == 12) {
        float s = bf[l * CC + c];
        for (int j = 0; j < CC; j++) s = fmaf(rf[j], eb[j], s);
        g_cf[l * CC + c] = s;
    } else {
        float s = bs[l * CC + c];
        for (int j = 0; j < CC; j++) s = fmaf(rs[j], eb[j], s);
        g_cs[l * CC + c] = s;
    }
}

// ---------------- build transposed concatenated node weights ----------------
// WcatT[l][k][q*128+c]; q=0:Wfi q=1:Wfj q=2:Wsi q=3:Wsj
__global__ void k_wcat(const float* __restrict__ Wf, const float* __restrict__ Ws) {
    int t = blockIdx.x * blockDim.x + threadIdx.x;
    if (t >= LL * CC * 4 * CC) return;
    int l = t / (CC * 4 * CC);
    int r = t % (CC * 4 * CC);
    int k = r / (4 * CC);
    int col = r % (4 * CC);
    int q = col >> 7;
    int c = col & 127;
    const float* base = (q < 2 ? Wf : Ws);
    float v = base[(size_t)(l * CC + c) * 3 * CC + ((q & 1) ? CC : 0) + k];
    g_WcatT[t] = v;
}

// ---------------- CSR build ----------------
__global__ void k_hist(const void* __restrict__ ei) {
    int e = blockIdx.x * blockDim.x + threadIdx.x;
    if (e >= EE) return;
    int dst = load_idx(ei, (long long)EE + e);
    atomicAdd(&g_deg[dst], 1);
}

__global__ void k_scan() {
    __shared__ int s_warp[32];
    __shared__ int s_total;
    const int tid = threadIdx.x;           // 1024 threads
    const int lane = tid & 31, wid = tid >> 5;
    int base = 0;
    for (int start = 0; start < NN; start += 8192) {
        int v[8];
        int run = 0;
#pragma unroll
        for (int i = 0; i < 8; i++) {
            int idx = start + tid * 8 + i;
            int t = (idx < NN) ? g_deg[idx] : 0;
            v[i] = run;
            run += t;
        }
        int incl = run;
#pragma unroll
        for (int d = 1; d < 32; d <<= 1) {
            int y = __shfl_up_sync(0xffffffffu, incl, d);
            if (lane >= d) incl += y;
        }
        if (lane == 31) s_warp[wid] = incl;
        __syncthreads();
        if (wid == 0) {
            int w = s_warp[lane];
            int wi = w;
#pragma unroll
            for (int d = 1; d < 32; d <<= 1) {
                int y = __shfl_up_sync(0xffffffffu, wi, d);
                if (lane >= d) wi += y;
            }
            s_warp[lane] = wi - w;  // exclusive
            if (lane == 31) s_total = wi;
        }
        __syncthreads();
        int toff = base + s_warp[wid] + (incl - run);
#pragma unroll
        for (int i = 0; i < 8; i++) {
            int idx = start + tid * 8 + i;
            if (idx < NN) {
                g_off[idx] = toff + v[i];
                g_cur[idx] = toff + v[i];
            }
        }
        base += s_total;
        __syncthreads();
    }
    if (tid == 0) g_off[NN] = base;
}

__global__ void k_scatter(const void* __restrict__ ei, const float* __restrict__ ea) {
    int e = blockIdx.x * blockDim.x + threadIdx.x;
    if (e >= EE) return;
    int dst = load_idx(ei, (long long)EE + e);
    int src = load_idx(ei, e);
    int pos = atomicAdd(&g_cur[dst], 1);
    g_srcs[pos] = src;
    const float* a = ea + (size_t)e * 6;
    float* o = g_eas + (size_t)pos * 6;
#pragma unroll
    for (int k = 0; k < 6; k++) o[k] = a[k];
}

// ---------------- per-layer node GEMM: T = h @ WcatT (M=NN, N=512, K=128) ----------------
__global__ void __launch_bounds__(256) k_gemm(int l) {
    __shared__ float As[16][132];  // [k][m], padded
    __shared__ float Bs[16][64];   // [k][n]
    const float* __restrict__ Bt = g_WcatT + (size_t)l * CC * 4 * CC;
    const int tid = threadIdx.x;
    const int tx = tid & 15, ty = tid >> 4;
    const int bm = blockIdx.x * 128;
    const int bn = blockIdx.y * 64;
    float acc[8][4];
#pragma unroll
    for (int i = 0; i < 8; i++)
#pragma unroll
        for (int j = 0; j < 4; j++) acc[i][j] = 0.f;

    for (int kk = 0; kk < CC; kk += 16) {
#pragma unroll
        for (int r = 0; r < 2; r++) {
            int idx = tid + r * 256;
            int row = idx >> 2;
            int q = (idx & 3) << 2;
            float4 a;
            if (bm + row < NN)
                a = *(const float4*)(g_h + (size_t)(bm + row) * CC + kk + q);
            else
                a = make_float4(0.f, 0.f, 0.f, 0.f);
            As[q + 0][row] = a.x;
            As[q + 1][row] = a.y;
            As[q + 2][row] = a.z;
            As[q + 3][row] = a.w;
        }
        {
            int k = tid >> 4, n4 = (tid & 15) << 2;
            *(float4*)&Bs[k][n4] = *(const float4*)(Bt + (size_t)(kk + k) * 512 + bn + n4);
        }
        __syncthreads();
#pragma unroll
        for (int k = 0; k < 16; k++) {
            float4 t0 = *(const float4*)&As[k][ty * 8];
            float4 t1 = *(const float4*)&As[k][ty * 8 + 4];
            float4 tb = *(const float4*)&Bs[k][tx * 4];
            float a0[8] = {t0.x, t0.y, t0.z, t0.w, t1.x, t1.y, t1.z, t1.w};
            float b0[4] = {tb.x, tb.y, tb.z, tb.w};
#pragma unroll
            for (int i = 0; i < 8; i++)
#pragma unroll
                for (int j = 0; j < 4; j++) acc[i][j] = fmaf(a0[i], b0[j], acc[i][j]);
        }
        __syncthreads();
    }
#pragma unroll
    for (int i = 0; i < 8; i++) {
        int row = bm + ty * 8 + i;
        if (row < NN) {
            float4 v = make_float4(acc[i][0], acc[i][1], acc[i][2], acc[i][3]);
            *(float4*)(g_T + (size_t)row * 512 + bn + tx * 4) = v;
        }
    }
}

// ---------------- per-layer aggregation (CSR gather-max) + BN + residual ----------------
__global__ void __launch_bounds__(256) k_agg(const float* __restrict__ gamma,
                                             const float* __restrict__ beta,
                                             const float* __restrict__ bmean,
                                             const float* __restrict__ bvar,
                                             int l) {
    __shared__ float4 sAf[6 * 32];
    __shared__ float4 sAs[6 * 32];
    __shared__ float4 sC[64];  // [0..31]=cf, [32..63]=cs
    int tid = threadIdx.x;
    if (tid < 192) {
        sAf[tid] = ((const float4*)(g_AfT + (size_t)l * 6 * CC))[tid];
        sAs[tid] = ((const float4*)(g_AsT + (size_t)l * 6 * CC))[tid];
    }
    if (tid < 32)
        sC[tid] = ((const float4*)(g_cf + (size_t)l * CC))[tid];
    else if (tid < 64)
        sC[tid] = ((const float4*)(g_cs + (size_t)l * CC))[tid - 32];
    __syncthreads();

    int lane = tid & 31;
    int n = (blockIdx.x * 256 + tid) >> 5;
    if (n >= NN) return;

    const float4* T4 = (const float4*)g_T;
    float4 fi = T4[(size_t)n * 128 + lane];        // hf_i[dst]
    float4 si = T4[(size_t)n * 128 + 64 + lane];   // hs_i[dst]
    float4 c0 = sC[lane], c1 = sC[32 + lane];
    fi.x += c0.x; fi.y += c0.y; fi.z += c0.z; fi.w += c0.w;
    si.x += c1.x; si.y += c1.y; si.z += c1.z; si.w += c1.w;

    float4 mx = make_float4(0.f, 0.f, 0.f, 0.f);
    int beg = g_off[n], end = g_off[n + 1];
    for (int j = beg; j < end; j++) {
        int s = g_srcs[j];
        float4 fj = T4[(size_t)s * 128 + 32 + lane];  // hf_j[src]
        float4 sj = T4[(size_t)s * 128 + 96 + lane];  // hs_j[src]
        const float* ap = g_eas + (size_t)j * 6;
        float a[6];
#pragma unroll
        for (int k = 0; k < 6; k++) a[k] = __ldg(ap + k);

        float4 zf, zs;
        zf.x = fi.x + fj.x; zf.y = fi.y + fj.y; zf.z = fi.z + fj.z; zf.w = fi.w + fj.w;
        zs.x = si.x + sj.x; zs.y = si.y + sj.y; zs.z = si.z + sj.z; zs.w = si.w + sj.w;
#pragma unroll
        for (int k = 0; k < 6; k++) {
            float4 wf = sAf[k * 32 + lane];
            zf.x = fmaf(a[k], wf.x, zf.x);
            zf.y = fmaf(a[k], wf.y, zf.y);
            zf.z = fmaf(a[k], wf.z, zf.z);
            zf.w = fmaf(a[k], wf.w, zf.w);
            float4 ws = sAs[k * 32 + lane];
            zs.x = fmaf(a[k], ws.x, zs.x);
            zs.y = fmaf(a[k], ws.y, zs.y);
            zs.z = fmaf(a[k], ws.z, zs.z);
            zs.w = fmaf(a[k], ws.w, zs.w);
        }
        float4 m;
        m.x = sigf(zf.x) * spf(zs.x);
        m.y = sigf(zf.y) * spf(zs.y);
        m.z = sigf(zf.z) * spf(zs.z);
        m.w = sigf(zf.w) * spf(zs.w);
        mx.x = fmaxf(mx.x, m.x);
        mx.y = fmaxf(mx.y, m.y);
        mx.z = fmaxf(mx.z, m.z);
        mx.w = fmaxf(mx.w, m.w);
    }

    float4 g4 = ((const float4*)(gamma + (size_t)l * CC))[lane];
    float4 b4 = ((const float4*)(beta + (size_t)l * CC))[lane];
    float4 m4 = ((const float4*)(bmean + (size_t)l * CC))[lane];
    float4 v4 = ((const float4*)(bvar + (size_t)l * CC))[lane];
    float4* H4 = (float4*)g_h;
    float4 h4 = H4[(size_t)n * 32 + lane];
    h4.x += (mx.x - m4.x) * rsqrtf(v4.x + 1e-5f) * g4.x + b4.x;
    h4.y += (mx.y - m4.y) * rsqrtf(v4.y + 1e-5f) * g4.y + b4.y;
    h4.z += (mx.z - m4.z) * rsqrtf(v4.z + 1e-5f) * g4.z + b4.z;
    h4.w += (mx.w - m4.w) * rsqrtf(v4.w + 1e-5f) * g4.w + b4.w;
    H4[(size_t)n * 32 + lane] = h4;
}

// ---------------- final head: logits = h @ lin_W.T + lin_b ----------------
__global__ void __launch_bounds__(256) k_final(const float* __restrict__ linW,
                                               const float* __restrict__ linb,
                                               float* __restrict__ out) {
    int tid = threadIdx.x;
    int lane = tid & 31;
    int n = (blockIdx.x * 256 + tid) >> 5;
    if (n >= NN) return;
    float4 h4 = ((const float4*)g_h)[(size_t)n * 32 + lane];
#pragma unroll
    for (int j = 0; j < KK; j++) {
        float4 w = ((const float4*)linW)[j * 32 + lane];
        float p = h4.x * w.x + h4.y * w.y + h4.z * w.z + h4.w * w.w;
#pragma unroll
        for (int d = 16; d; d >>= 1) p += __shfl_xor_sync(0xffffffffu, p, d);
        if (lane == 0) out[(size_t)n * KK + j] = p + __ldg(linb + j);
    }
}

__global__ void k_copy_h(float* __restrict__ out) {
    int i = blockIdx.x * blockDim.x + threadIdx.x;
    if (i < NN * CC / 4) ((float4*)out)[i] = ((const float4*)g_h)[i];
}

// ---------------- launch ----------------
extern "C" void kernel_launch(void* const* d_in, const int* in_sizes, int n_in,
                              void* d_out, int out_size) {
    const float* x       = (const float*)d_in[0];
    const void*  ei      = d_in[1];
    const float* ea      = (const float*)d_in[2];
    const float* node_W  = (const float*)d_in[3];
    const float* node_b  = (const float*)d_in[4];
    const float* edge_W  = (const float*)d_in[5];
    const float* edge_b  = (const float*)d_in[6];
    const float* Wf      = (const float*)d_in[7];
    const float* bf      = (const float*)d_in[8];
    const float* Ws      = (const float*)d_in[9];
    const float* bs      = (const float*)d_in[10];
    const float* gamma   = (const float*)d_in[11];
    const float* beta    = (const float*)d_in[12];
    const float* bn_mean = (const float*)d_in[13];
    const float* bn_var  = (const float*)d_in[14];
    const float* lin_W   = (const float*)d_in[15];
    const float* lin_b   = (const float*)d_in[16];
    float* out = (float*)d_out;

    k_detect<<<1, 256>>>((const int*)ei);
    k_zero_deg<<<(NN + 256) / 256 + 1, 256>>>();
    k_node_encode<<<(NN * CC + 255) / 256, 256>>>(x, node_W, node_b);
    k_fold<<<(LL * CC * 14 + 255) / 256, 256>>>(Wf, bf, Ws, bs, edge_W, edge_b);
    k_wcat<<<(LL * CC * 4 * CC + 255) / 256, 256>>>(Wf, Ws);
    k_hist<<<(EE + 255) / 256, 256>>>(ei);
    k_scan<<<1, 1024>>>();
    k_scatter<<<(EE + 255) / 256, 256>>>(ei, ea);

    dim3 ggrid((NN + 127) / 128, 4 * CC / 64);
    for (int l = 0; l < LL; l++) {
        k_gemm<<<ggrid, 256>>>(l);
        k_agg<<<(NN * 32 + 255) / 256, 256>>>(gamma, beta, bn_mean, bn_var, l);
    }

    k_final<<<(NN * 32 + 255) / 256, 256>>>(lin_W, lin_b, out);
    k_copy_h<<<(NN * CC / 4 + 255) / 256, 256>>>(out + (size_t)NN * KK);
}

// round 3
// speedup vs baseline: 1.2936x; 1.2936x over previous
#include <cuda_runtime.h>
#include <cstdint>

#define NN 50000
#define EE 800000
#define CC 128
#define LL 3
#define KK 10

// ---------------- scratch ----------------
__device__ __align__(16) float g_h[NN * CC];                  // 25.6 MB
__device__ __align__(16) float g_T[(size_t)NN * 512];         // 102.4 MB: [hf_i|hf_j|hs_i|hs_j]
__device__ __align__(16) float g_Bcat[LL * 512 * CC];         // [l][n][k] K-major weight rows
__device__ __align__(16) float g_AfT[LL * 6 * CC];
__device__ __align__(16) float g_AsT[LL * 6 * CC];
__device__ __align__(16) float g_cf[LL * CC];
__device__ __align__(16) float g_cs[LL * CC];
__device__ int   g_deg[NN + 1];
__device__ int   g_off[NN + 1];
__device__ int   g_cur[NN];
__device__ int   g_srcs[EE];
__device__ __align__(16) float g_eas[(size_t)EE * 6];
__device__ int   g_is64;

// ---------------- math helpers ----------------
__device__ __forceinline__ float sigf(float z) { return __fdividef(1.f, 1.f + __expf(-z)); }
__device__ __forceinline__ float spf(float z) { return fmaxf(z, 0.f) + __logf(1.f + __expf(-fabsf(z))); }

__device__ __forceinline__ uint32_t f2tf32(float f) {
    uint32_t o;
    asm("cvt.rna.tf32.f32 %0, %1;" : "=r"(o) : "f"(f));
    return o;
}

__device__ __forceinline__ void mma_tf32(float* d, const uint32_t* a, const uint32_t* b) {
    asm volatile(
        "mma.sync.aligned.m16n8k8.row.col.f32.tf32.tf32.f32 "
        "{%0,%1,%2,%3}, {%4,%5,%6,%7}, {%8,%9}, {%0,%1,%2,%3};"
        : "+f"(d[0]), "+f"(d[1]), "+f"(d[2]), "+f"(d[3])
        : "r"(a[0]), "r"(a[1]), "r"(a[2]), "r"(a[3]), "r"(b[0]), "r"(b[1]));
}

// ---------------- detect int32 vs int64 edge_index ----------------
__global__ void k_detect(const int* __restrict__ ei32) {
    __shared__ int any;
    if (threadIdx.x == 0) any = 0;
    __syncthreads();
    for (int i = threadIdx.x; i < 4096; i += blockDim.x)
        if (ei32[2 * i + 1] != 0) any = 1;
    __syncthreads();
    if (threadIdx.x == 0) g_is64 = (any == 0) ? 1 : 0;
}
__device__ __forceinline__ int load_idx(const void* ei, long long pos) {
    if (g_is64) return (int)(((const long long*)ei)[pos]);
    return ((const int*)ei)[pos];
}

// ---------------- fused setup: zero_deg | fold | bprep | node_encode ----------------
#define ZB 196
#define FB 21
#define WB 768
#define NB 25000
__global__ void k_setup(const float* __restrict__ x, const float* __restrict__ nW,
                        const float* __restrict__ nb,
                        const float* __restrict__ Wf, const float* __restrict__ bf,
                        const float* __restrict__ Ws, const float* __restrict__ bs,
                        const float* __restrict__ eW, const float* __restrict__ eb) {
    int b = blockIdx.x, tid = threadIdx.x;
    if (b < ZB) {
        int i = b * 256 + tid;
        if (i <= NN) g_deg[i] = 0;
    } else if (b < ZB + FB) {
        int t = (b - ZB) * 256 + tid;
        if (t >= LL * CC * 14) return;
        int l = t / (CC * 14);
        int r = t % (CC * 14);
        int c = r / 14, kk = r % 14;
        const float* rf = Wf + ((size_t)(l * CC + c) * 3 * CC) + 2 * CC;
        const float* rs = Ws + ((size_t)(l * CC + c) * 3 * CC) + 2 * CC;
        if (kk < 6) {
            float s = 0.f;
            for (int j = 0; j < CC; j++) s = fmaf(rf[j], eW[j * 6 + kk], s);
            g_AfT[l * 6 * CC + kk * CC + c] = s;
        } else if (kk < 12) {
            int k = kk - 6;
            float s = 0.f;
            for (int j = 0; j < CC; j++) s = fmaf(rs[j], eW[j * 6 + k], s);
            g_AsT[l * 6 * CC + k * CC + c] = s;
        } else if (kk == 12) {
            float s = bf[l * CC + c];
            for (int j = 0; j < CC; j++) s = fmaf(rf[j], eb[j], s);
            g_cf[l * CC + c] = s;
        } else {
            float s = bs[l * CC + c];
            for (int j = 0; j < CC; j++) s = fmaf(rs[j], eb[j], s);
            g_cs[l * CC + c] = s;
        }
    } else if (b < ZB + FB + WB) {
        int t = (b - ZB - FB) * 256 + tid;  // over LL*512*128
        int l = t / (512 * CC);
        int r = t % (512 * CC);
        int n = r / CC, k = r % CC;
        int q = n >> 7, c = n & 127;
        const float* base = (q < 2 ? Wf : Ws);
        g_Bcat[t] = base[(size_t)(l * CC + c) * 3 * CC + ((q & 1) ? CC : 0) + k];
    } else {
        int i = (b - ZB - FB - WB) * 256 + tid;  // NN*CC exactly
        int n = i / CC, c = i % CC;
        const float* xr = x + (size_t)n * 7;
        const float* wr = nW + (size_t)c * 7;
        float acc = nb[c];
#pragma unroll
        for (int k = 0; k < 7; k++) acc = fmaf(xr[k], wr[k], acc);
        g_h[i] = acc;
    }
}

// ---------------- CSR build ----------------
__global__ void k_hist(const void* __restrict__ ei) {
    int e = blockIdx.x * blockDim.x + threadIdx.x;
    if (e >= EE) return;
    atomicAdd(&g_deg[load_idx(ei, (long long)EE + e)], 1);
}

__global__ void k_scan() {
    __shared__ int s_warp[32];
    __shared__ int s_total;
    const int tid = threadIdx.x;  // 1024
    const int lane = tid & 31, wid = tid >> 5;
    int base = 0;
    for (int start = 0; start < NN; start += 8192) {
        int v[8];
        int run = 0;
#pragma unroll
        for (int i = 0; i < 8; i++) {
            int idx = start + tid * 8 + i;
            int t = (idx < NN) ? g_deg[idx] : 0;
            v[i] = run;
            run += t;
        }
        int incl = run;
#pragma unroll
        for (int d = 1; d < 32; d <<= 1) {
            int y = __shfl_up_sync(0xffffffffu, incl, d);
            if (lane >= d) incl += y;
        }
        if (lane == 31) s_warp[wid] = incl;
        __syncthreads();
        if (wid == 0) {
            int w = s_warp[lane];
            int wi = w;
#pragma unroll
            for (int d = 1; d < 32; d <<= 1) {
                int y = __shfl_up_sync(0xffffffffu, wi, d);
                if (lane >= d) wi += y;
            }
            s_warp[lane] = wi - w;
            if (lane == 31) s_total = wi;
        }
        __syncthreads();
        int toff = base + s_warp[wid] + (incl - run);
#pragma unroll
        for (int i = 0; i < 8; i++) {
            int idx = start + tid * 8 + i;
            if (idx < NN) {
                g_off[idx] = toff + v[i];
                g_cur[idx] = toff + v[i];
            }
        }
        base += s_total;
        __syncthreads();
    }
    if (tid == 0) g_off[NN] = base;
}

__global__ void k_scatter(const void* __restrict__ ei, const float* __restrict__ ea) {
    int e = blockIdx.x * blockDim.x + threadIdx.x;
    if (e >= EE) return;
    int dst = load_idx(ei, (long long)EE + e);
    int src = load_idx(ei, e);
    int pos = atomicAdd(&g_cur[dst], 1);
    g_srcs[pos] = src;
    const float* a = ea + (size_t)e * 6;
    float* o = g_eas + (size_t)pos * 6;
#pragma unroll
    for (int k = 0; k < 6; k++) o[k] = a[k];
}

// ---------------- mma.sync tf32 GEMM: T = h @ Bcat^T (M=NN, N=512, K=128) ----------------
// CTA: 128 rows x 128 cols, K=128 resident. 8 warps, warp tile 32x64.
#define LDA 132
#define SMEM_MMA (2 * 128 * LDA * 4)

__global__ void __launch_bounds__(256) k_mma(int l) {
    extern __shared__ uint32_t smem_u[];
    uint32_t* sA = smem_u;               // [128][LDA]  row(m) x k
    uint32_t* sB = smem_u + 128 * LDA;   // [128][LDA]  col(n) x k
    const int tid = threadIdx.x;
    const int wid = tid >> 5, lane = tid & 31;
    const int bm = blockIdx.x * 128;
    const int bn = blockIdx.y * 128;

    // load A (h tile) with tf32 convert
#pragma unroll
    for (int i = 0; i < 16; i++) {
        int idx = tid + i * 256;          // 4096 float4s
        int row = idx >> 5;
        int col = (idx & 31) << 2;
        float4 v = make_float4(0.f, 0.f, 0.f, 0.f);
        if (bm + row < NN) v = *(const float4*)(g_h + (size_t)(bm + row) * CC + col);
        uint32_t* d = sA + row * LDA + col;
        d[0] = f2tf32(v.x); d[1] = f2tf32(v.y); d[2] = f2tf32(v.z); d[3] = f2tf32(v.w);
    }
    // load B (weight rows) with tf32 convert
    const float* Bsrc = g_Bcat + ((size_t)l * 512 + bn) * CC;
#pragma unroll
    for (int i = 0; i < 16; i++) {
        int idx = tid + i * 256;
        int row = idx >> 5;
        int col = (idx & 31) << 2;
        float4 v = *(const float4*)(Bsrc + (size_t)row * CC + col);
        uint32_t* d = sB + row * LDA + col;
        d[0] = f2tf32(v.x); d[1] = f2tf32(v.y); d[2] = f2tf32(v.z); d[3] = f2tf32(v.w);
    }
    __syncthreads();

    const int wm = (wid >> 1) * 32;   // warp row offset (0,32,64,96)
    const int wn = (wid & 1) * 64;    // warp col offset (0,64)
    const int gr = lane >> 2;         // group row 0..7
    const int tg = lane & 3;          // thread in group 0..3

    float acc[2][8][4];
#pragma unroll
    for (int mi = 0; mi < 2; mi++)
#pragma unroll
        for (int ni = 0; ni < 8; ni++)
#pragma unroll
            for (int q = 0; q < 4; q++) acc[mi][ni][q] = 0.f;

#pragma unroll
    for (int ks = 0; ks < 16; ks++) {
        const int k0 = ks * 8;
        uint32_t a[2][4];
#pragma unroll
        for (int mi = 0; mi < 2; mi++) {
            const uint32_t* ap = sA + (wm + mi * 16 + gr) * LDA + k0 + tg;
            a[mi][0] = ap[0];
            a[mi][1] = ap[8 * LDA];
            a[mi][2] = ap[4];
            a[mi][3] = ap[8 * LDA + 4];
        }
        uint32_t b[8][2];
#pragma unroll
        for (int ni = 0; ni < 8; ni++) {
            const uint32_t* bp = sB + (wn + ni * 8 + gr) * LDA + k0 + tg;
            b[ni][0] = bp[0];
            b[ni][1] = bp[4];
        }
#pragma unroll
        for (int mi = 0; mi < 2; mi++)
#pragma unroll
            for (int ni = 0; ni < 8; ni++)
                mma_tf32(acc[mi][ni], a[mi], b[ni]);
    }

    // epilogue: direct stores (float2 per fragment row)
#pragma unroll
    for (int mi = 0; mi < 2; mi++) {
        int r0 = bm + wm + mi * 16 + gr;
        int r1 = r0 + 8;
#pragma unroll
        for (int ni = 0; ni < 8; ni++) {
            int col = bn + wn + ni * 8 + tg * 2;
            if (r0 < NN) *(float2*)(g_T + (size_t)r0 * 512 + col) = make_float2(acc[mi][ni][0], acc[mi][ni][1]);
            if (r1 < NN) *(float2*)(g_T + (size_t)r1 * 512 + col) = make_float2(acc[mi][ni][2], acc[mi][ni][3]);
        }
    }
}

// ---------------- per-layer aggregation (CSR gather-max) + BN + residual ----------------
__global__ void __launch_bounds__(256) k_agg(const float* __restrict__ gamma,
                                             const float* __restrict__ beta,
                                             const float* __restrict__ bmean,
                                             const float* __restrict__ bvar,
                                             int l) {
    __shared__ float4 sAf[6 * 32];
    __shared__ float4 sAs[6 * 32];
    __shared__ float4 sC[64];
    int tid = threadIdx.x;
    if (tid < 192) {
        sAf[tid] = ((const float4*)(g_AfT + (size_t)l * 6 * CC))[tid];
        sAs[tid] = ((const float4*)(g_AsT + (size_t)l * 6 * CC))[tid];
    }
    if (tid < 32)
        sC[tid] = ((const float4*)(g_cf + (size_t)l * CC))[tid];
    else if (tid < 64)
        sC[tid] = ((const float4*)(g_cs + (size_t)l * CC))[tid - 32];
    __syncthreads();

    int lane = tid & 31;
    int n = (blockIdx.x * 256 + tid) >> 5;
    if (n >= NN) return;

    const float4* T4 = (const float4*)g_T;
    float4 fi = T4[(size_t)n * 128 + lane];
    float4 si = T4[(size_t)n * 128 + 64 + lane];
    float4 c0 = sC[lane], c1 = sC[32 + lane];
    fi.x += c0.x; fi.y += c0.y; fi.z += c0.z; fi.w += c0.w;
    si.x += c1.x; si.y += c1.y; si.z += c1.z; si.w += c1.w;

    float4 mx = make_float4(0.f, 0.f, 0.f, 0.f);
    int beg = g_off[n], end = g_off[n + 1];
    for (int j = beg; j < end; j++) {
        int s = g_srcs[j];
        float4 fj = T4[(size_t)s * 128 + 32 + lane];
        float4 sj = T4[(size_t)s * 128 + 96 + lane];
        const float* ap = g_eas + (size_t)j * 6;
        float a[6];
#pragma unroll
        for (int k = 0; k < 6; k++) a[k] = __ldg(ap + k);

        float4 zf, zs;
        zf.x = fi.x + fj.x; zf.y = fi.y + fj.y; zf.z = fi.z + fj.z; zf.w = fi.w + fj.w;
        zs.x = si.x + sj.x; zs.y = si.y + sj.y; zs.z = si.z + sj.z; zs.w = si.w + sj.w;
#pragma unroll
        for (int k = 0; k < 6; k++) {
            float4 wf = sAf[k * 32 + lane];
            zf.x = fmaf(a[k], wf.x, zf.x);
            zf.y = fmaf(a[k], wf.y, zf.y);
            zf.z = fmaf(a[k], wf.z, zf.z);
            zf.w = fmaf(a[k], wf.w, zf.w);
            float4 ws = sAs[k * 32 + lane];
            zs.x = fmaf(a[k], ws.x, zs.x);
            zs.y = fmaf(a[k], ws.y, zs.y);
            zs.z = fmaf(a[k], ws.z, zs.z);
            zs.w = fmaf(a[k], ws.w, zs.w);
        }
        float4 m;
        m.x = sigf(zf.x) * spf(zs.x);
        m.y = sigf(zf.y) * spf(zs.y);
        m.z = sigf(zf.z) * spf(zs.z);
        m.w = sigf(zf.w) * spf(zs.w);
        mx.x = fmaxf(mx.x, m.x);
        mx.y = fmaxf(mx.y, m.y);
        mx.z = fmaxf(mx.z, m.z);
        mx.w = fmaxf(mx.w, m.w);
    }

    float4 g4 = ((const float4*)(gamma + (size_t)l * CC))[lane];
    float4 b4 = ((const float4*)(beta + (size_t)l * CC))[lane];
    float4 m4 = ((const float4*)(bmean + (size_t)l * CC))[lane];
    float4 v4 = ((const float4*)(bvar + (size_t)l * CC))[lane];
    float4* H4 = (float4*)g_h;
    float4 h4 = H4[(size_t)n * 32 + lane];
    h4.x += (mx.x - m4.x) * rsqrtf(v4.x + 1e-5f) * g4.x + b4.x;
    h4.y += (mx.y - m4.y) * rsqrtf(v4.y + 1e-5f) * g4.y + b4.y;
    h4.z += (mx.z - m4.z) * rsqrtf(v4.z + 1e-5f) * g4.z + b4.z;
    h4.w += (mx.w - m4.w) * rsqrtf(v4.w + 1e-5f) * g4.w + b4.w;
    H4[(size_t)n * 32 + lane] = h4;
}

// ---------------- final head ----------------
__global__ void __launch_bounds__(256) k_final(const float* __restrict__ linW,
                                               const float* __restrict__ linb,
                                               float* __restrict__ out) {
    int tid = threadIdx.x;
    int lane = tid & 31;
    int n = (blockIdx.x * 256 + tid) >> 5;
    if (n >= NN) return;
    float4 h4 = ((const float4*)g_h)[(size_t)n * 32 + lane];
#pragma unroll
    for (int j = 0; j < KK; j++) {
        float4 w = ((const float4*)linW)[j * 32 + lane];
        float p = h4.x * w.x + h4.y * w.y + h4.z * w.z + h4.w * w.w;
#pragma unroll
        for (int d = 16; d; d >>= 1) p += __shfl_xor_sync(0xffffffffu, p, d);
        if (lane == 0) out[(size_t)n * KK + j] = p + __ldg(linb + j);
    }
}

__global__ void k_copy_h(float* __restrict__ out) {
    int i = blockIdx.x * blockDim.x + threadIdx.x;
    if (i < NN * CC / 4) ((float4*)out)[i] = ((const float4*)g_h)[i];
}

// ---------------- launch ----------------
extern "C" void kernel_launch(void* const* d_in, const int* in_sizes, int n_in,
                              void* d_out, int out_size) {
    const float* x       = (const float*)d_in[0];
    const void*  ei      = d_in[1];
    const float* ea      = (const float*)d_in[2];
    const float* node_W  = (const float*)d_in[3];
    const float* node_b  = (const float*)d_in[4];
    const float* edge_W  = (const float*)d_in[5];
    const float* edge_b  = (const float*)d_in[6];
    const float* Wf      = (const float*)d_in[7];
    const float* bf      = (const float*)d_in[8];
    const float* Ws      = (const float*)d_in[9];
    const float* bs      = (const float*)d_in[10];
    const float* gamma   = (const float*)d_in[11];
    const float* beta    = (const float*)d_in[12];
    const float* bn_mean = (const float*)d_in[13];
    const float* bn_var  = (const float*)d_in[14];
    const float* lin_W   = (const float*)d_in[15];
    const float* lin_b   = (const float*)d_in[16];
    float* out = (float*)d_out;

    cudaFuncSetAttribute(k_mma, cudaFuncAttributeMaxDynamicSharedMemorySize, SMEM_MMA);

    k_detect<<<1, 256>>>((const int*)ei);
    k_setup<<<ZB + FB + WB + NB, 256>>>(x, node_W, node_b, Wf, bf, Ws, bs, edge_W, edge_b);
    k_hist<<<(EE + 255) / 256, 256>>>(ei);
    k_scan<<<1, 1024>>>();
    k_scatter<<<(EE + 255) / 256, 256>>>(ei, ea);

    dim3 ggrid((NN + 127) / 128, 4);
    for (int l = 0; l < LL; l++) {
        k_mma<<<ggrid, 256, SMEM_MMA>>>(l);
        k_agg<<<(NN * 32 + 255) / 256, 256>>>(gamma, beta, bn_mean, bn_var, l);
    }

    k_final<<<(NN * 32 + 255) / 256, 256>>>(lin_W, lin_b, out);
    k_copy_h<<<(NN * CC / 4 + 255) / 256, 256>>>(out + (size_t)NN * KK);
}

// round 4
// speedup vs baseline: 1.5691x; 1.2129x over previous
#include <cuda_runtime.h>
#include <cuda_fp16.h>
#include <cstdint>

#define NN 50000
#define EE 800000
#define CC 128
#define LL 3
#define KK 10

// ---------------- scratch ----------------
__device__ __align__(16) float g_h[NN * CC];                  // 25.6 MB
__device__ __align__(16) float g_T[(size_t)NN * 512];         // 102.4 MB
__device__ __align__(16) float g_Bcat[LL * 512 * CC];
__device__ __align__(16) float g_AfT[LL * 6 * CC];
__device__ __align__(16) float g_AsT[LL * 6 * CC];
__device__ __align__(16) float g_cf[LL * CC];
__device__ __align__(16) float g_cs[LL * CC];
__device__ int   g_deg[NN + 1];
__device__ int   g_off[NN + 1];
__device__ int   g_cur[NN];
__device__ int   g_srcs[EE];
__device__ __align__(16) uint4 g_eash[EE];   // 6 halves (packed) per edge
__device__ int   g_bsum[64];
__device__ int   g_is64;

// ---------------- math helpers ----------------
__device__ __forceinline__ float tanh_fast(float x) {
    float r;
    asm("tanh.approx.f32 %0, %1;" : "=f"(r) : "f"(x));
    return r;
}
__device__ __forceinline__ float msg1(float zf, float zs) {
    float sg = fmaf(tanh_fast(0.5f * zf), 0.5f, 0.5f);
    float e = __expf(-fabsf(zs));
    float sp = fmaxf(zs, 0.f) + __logf(1.f + e);
    return sg * sp;
}

__device__ __forceinline__ uint32_t f2tf32(float f) {
    uint32_t o;
    asm("cvt.rna.tf32.f32 %0, %1;" : "=r"(o) : "f"(f));
    return o;
}
__device__ __forceinline__ void mma_tf32(float* d, const uint32_t* a, const uint32_t* b) {
    asm volatile(
        "mma.sync.aligned.m16n8k8.row.col.f32.tf32.tf32.f32 "
        "{%0,%1,%2,%3}, {%4,%5,%6,%7}, {%8,%9}, {%0,%1,%2,%3};"
        : "+f"(d[0]), "+f"(d[1]), "+f"(d[2]), "+f"(d[3])
        : "r"(a[0]), "r"(a[1]), "r"(a[2]), "r"(a[3]), "r"(b[0]), "r"(b[1]));
}

// ---------------- detect int32 vs int64 edge_index ----------------
__global__ void k_detect(const int* __restrict__ ei32) {
    __shared__ int any;
    if (threadIdx.x == 0) any = 0;
    __syncthreads();
    for (int i = threadIdx.x; i < 4096; i += blockDim.x)
        if (ei32[2 * i + 1] != 0) any = 1;
    __syncthreads();
    if (threadIdx.x == 0) g_is64 = (any == 0) ? 1 : 0;
}
__device__ __forceinline__ int load_idx(const void* ei, long long pos) {
    if (g_is64) return (int)(((const long long*)ei)[pos]);
    return ((const int*)ei)[pos];
}

// ---------------- fused setup: zero_deg | fold | bprep | node_encode ----------------
#define ZB 196
#define FB 21
#define WB 768
#define NB 25000
__global__ void k_setup(const float* __restrict__ x, const float* __restrict__ nW,
                        const float* __restrict__ nb,
                        const float* __restrict__ Wf, const float* __restrict__ bf,
                        const float* __restrict__ Ws, const float* __restrict__ bs,
                        const float* __restrict__ eW, const float* __restrict__ eb) {
    int b = blockIdx.x, tid = threadIdx.x;
    if (b < ZB) {
        int i = b * 256 + tid;
        if (i <= NN) g_deg[i] = 0;
    } else if (b < ZB + FB) {
        int t = (b - ZB) * 256 + tid;
        if (t >= LL * CC * 14) return;
        int l = t / (CC * 14);
        int r = t % (CC * 14);
        int c = r / 14, kk = r % 14;
        const float* rf = Wf + ((size_t)(l * CC + c) * 3 * CC) + 2 * CC;
        const float* rs = Ws + ((size_t)(l * CC + c) * 3 * CC) + 2 * CC;
        if (kk < 6) {
            float s = 0.f;
            for (int j = 0; j < CC; j++) s = fmaf(rf[j], eW[j * 6 + kk], s);
            g_AfT[l * 6 * CC + kk * CC + c] = s;
        } else if (kk < 12) {
            int k = kk - 6;
            float s = 0.f;
            for (int j = 0; j < CC; j++) s = fmaf(rs[j], eW[j * 6 + k], s);
            g_AsT[l * 6 * CC + k * CC + c] = s;
        } else if (kk == 12) {
            float s = bf[l * CC + c];
            for (int j = 0; j < CC; j++) s = fmaf(rf[j], eb[j], s);
            g_cf[l * CC + c] = s;
        } else {
            float s = bs[l * CC + c];
            for (int j = 0; j < CC; j++) s = fmaf(rs[j], eb[j], s);
            g_cs[l * CC + c] = s;
        }
    } else if (b < ZB + FB + WB) {
        int t = (b - ZB - FB) * 256 + tid;
        int l = t / (512 * CC);
        int r = t % (512 * CC);
        int n = r / CC, k = r % CC;
        int q = n >> 7, c = n & 127;
        const float* base = (q < 2 ? Wf : Ws);
        g_Bcat[t] = base[(size_t)(l * CC + c) * 3 * CC + ((q & 1) ? CC : 0) + k];
    } else {
        int i = (b - ZB - FB - WB) * 256 + tid;
        int n = i / CC, c = i % CC;
        const float* xr = x + (size_t)n * 7;
        const float* wr = nW + (size_t)c * 7;
        float acc = nb[c];
#pragma unroll
        for (int k = 0; k < 7; k++) acc = fmaf(xr[k], wr[k], acc);
        g_h[i] = acc;
    }
}

// ---------------- CSR build ----------------
__global__ void k_hist(const void* __restrict__ ei) {
    int e = blockIdx.x * blockDim.x + threadIdx.x;
    if (e >= EE) return;
    atomicAdd(&g_deg[load_idx(ei, (long long)EE + e)], 1);
}

// 3-phase scan over g_deg[0..NN] (deg[NN]==0) -> exclusive prefix in g_off
#define SC_NB 50
__global__ void __launch_bounds__(256) k_scan1() {
    __shared__ int sw[8];
    int b = blockIdx.x, tid = threadIdx.x, lane = tid & 31, wid = tid >> 5;
    int base = b * 1024 + tid * 4;
    int v[4];
    int run = 0;
#pragma unroll
    for (int i = 0; i < 4; i++) {
        int idx = base + i;
        int t = (idx <= NN) ? g_deg[idx] : 0;
        v[i] = run;
        run += t;
    }
    int incl = run;
#pragma unroll
    for (int d = 1; d < 32; d <<= 1) {
        int y = __shfl_up_sync(0xffffffffu, incl, d);
        if (lane >= d) incl += y;
    }
    if (lane == 31) sw[wid] = incl;
    __syncthreads();
    if (tid < 8) {
        int w = sw[tid];
        int wi = w;
#pragma unroll
        for (int d = 1; d < 8; d <<= 1) {
            int y = __shfl_up_sync(0xffu, wi, d);
            if (tid >= d) wi += y;
        }
        sw[tid] = wi - w;
        if (tid == 7) g_bsum[b] = wi;
    }
    __syncthreads();
    int off0 = sw[wid] + (incl - run);
#pragma unroll
    for (int i = 0; i < 4; i++) {
        int idx = base + i;
        if (idx <= NN) g_off[idx] = off0 + v[i];
    }
}

__global__ void k_scan2() {
    int lane = threadIdx.x;  // 32
    int e0 = (2 * lane < SC_NB) ? g_bsum[2 * lane] : 0;
    int e1 = (2 * lane + 1 < SC_NB) ? g_bsum[2 * lane + 1] : 0;
    int s = e0 + e1;
    int incl = s;
#pragma unroll
    for (int d = 1; d < 32; d <<= 1) {
        int y = __shfl_up_sync(0xffffffffu, incl, d);
        if (lane >= d) incl += y;
    }
    int excl = incl - s;
    if (2 * lane < SC_NB) g_bsum[2 * lane] = excl;
    if (2 * lane + 1 < SC_NB) g_bsum[2 * lane + 1] = excl + e0;
}

__global__ void __launch_bounds__(256) k_scan3() {
    int b = blockIdx.x, tid = threadIdx.x;
    int add = g_bsum[b];
#pragma unroll
    for (int i = 0; i < 4; i++) {
        int idx = b * 1024 + tid * 4 + i;
        if (idx <= NN) {
            int o = g_off[idx] + add;
            g_off[idx] = o;
            if (idx < NN) g_cur[idx] = o;
        }
    }
}

__global__ void k_scatter(const void* __restrict__ ei, const float* __restrict__ ea) {
    int e = blockIdx.x * blockDim.x + threadIdx.x;
    if (e >= EE) return;
    int dst = load_idx(ei, (long long)EE + e);
    int src = load_idx(ei, e);
    int pos = atomicAdd(&g_cur[dst], 1);
    g_srcs[pos] = src;
    const float* a = ea + (size_t)e * 6;
    half2 x01 = __floats2half2_rn(a[0], a[1]);
    half2 x23 = __floats2half2_rn(a[2], a[3]);
    half2 x45 = __floats2half2_rn(a[4], a[5]);
    uint4 u;
    u.x = *(uint32_t*)&x01;
    u.y = *(uint32_t*)&x23;
    u.z = *(uint32_t*)&x45;
    u.w = 0;
    g_eash[pos] = u;
}

// ---------------- mma.sync tf32 GEMM: T = h @ Bcat^T (M=NN, N=512, K=128) ----------------
#define LDA 132
#define SMEM_MMA (2 * 128 * LDA * 4)

__global__ void __launch_bounds__(256) k_mma(int l) {
    extern __shared__ uint32_t smem_u[];
    uint32_t* sA = smem_u;
    uint32_t* sB = smem_u + 128 * LDA;
    const int tid = threadIdx.x;
    const int wid = tid >> 5, lane = tid & 31;
    const int bm = blockIdx.x * 128;
    const int bn = blockIdx.y * 128;

#pragma unroll
    for (int i = 0; i < 16; i++) {
        int idx = tid + i * 256;
        int row = idx >> 5;
        int col = (idx & 31) << 2;
        float4 v = make_float4(0.f, 0.f, 0.f, 0.f);
        if (bm + row < NN) v = *(const float4*)(g_h + (size_t)(bm + row) * CC + col);
        uint32_t* d = sA + row * LDA + col;
        d[0] = f2tf32(v.x); d[1] = f2tf32(v.y); d[2] = f2tf32(v.z); d[3] = f2tf32(v.w);
    }
    const float* Bsrc = g_Bcat + ((size_t)l * 512 + bn) * CC;
#pragma unroll
    for (int i = 0; i < 16; i++) {
        int idx = tid + i * 256;
        int row = idx >> 5;
        int col = (idx & 31) << 2;
        float4 v = *(const float4*)(Bsrc + (size_t)row * CC + col);
        uint32_t* d = sB + row * LDA + col;
        d[0] = f2tf32(v.x); d[1] = f2tf32(v.y); d[2] = f2tf32(v.z); d[3] = f2tf32(v.w);
    }
    __syncthreads();

    const int wm = (wid >> 1) * 32;
    const int wn = (wid & 1) * 64;
    const int gr = lane >> 2;
    const int tg = lane & 3;

    float acc[2][8][4];
#pragma unroll
    for (int mi = 0; mi < 2; mi++)
#pragma unroll
        for (int ni = 0; ni < 8; ni++)
#pragma unroll
            for (int q = 0; q < 4; q++) acc[mi][ni][q] = 0.f;

#pragma unroll
    for (int ks = 0; ks < 16; ks++) {
        const int k0 = ks * 8;
        uint32_t a[2][4];
#pragma unroll
        for (int mi = 0; mi < 2; mi++) {
            const uint32_t* ap = sA + (wm + mi * 16 + gr) * LDA + k0 + tg;
            a[mi][0] = ap[0];
            a[mi][1] = ap[8 * LDA];
            a[mi][2] = ap[4];
            a[mi][3] = ap[8 * LDA + 4];
        }
        uint32_t b[8][2];
#pragma unroll
        for (int ni = 0; ni < 8; ni++) {
            const uint32_t* bp = sB + (wn + ni * 8 + gr) * LDA + k0 + tg;
            b[ni][0] = bp[0];
            b[ni][1] = bp[4];
        }
#pragma unroll
        for (int mi = 0; mi < 2; mi++)
#pragma unroll
            for (int ni = 0; ni < 8; ni++)
                mma_tf32(acc[mi][ni], a[mi], b[ni]);
    }

#pragma unroll
    for (int mi = 0; mi < 2; mi++) {
        int r0 = bm + wm + mi * 16 + gr;
        int r1 = r0 + 8;
#pragma unroll
        for (int ni = 0; ni < 8; ni++) {
            int col = bn + wn + ni * 8 + tg * 2;
            if (r0 < NN) *(float2*)(g_T + (size_t)r0 * 512 + col) = make_float2(acc[mi][ni][0], acc[mi][ni][1]);
            if (r1 < NN) *(float2*)(g_T + (size_t)r1 * 512 + col) = make_float2(acc[mi][ni][2], acc[mi][ni][3]);
        }
    }
}

// ---------------- per-layer aggregation (CSR gather-max) + BN + residual ----------------
__global__ void __launch_bounds__(256) k_agg(const float* __restrict__ gamma,
                                             const float* __restrict__ beta,
                                             const float* __restrict__ bmean,
                                             const float* __restrict__ bvar,
                                             int l) {
    __shared__ half2 sAfa[192], sAfb[192], sAsa[192], sAsb[192];
    __shared__ float4 sC[64];
    int tid = threadIdx.x;
    if (tid < 192) {
        int k = tid >> 5, ln = tid & 31;
        const float* Af = g_AfT + (size_t)l * 6 * CC + k * CC + 4 * ln;
        const float* As_ = g_AsT + (size_t)l * 6 * CC + k * CC + 4 * ln;
        sAfa[tid] = __floats2half2_rn(Af[0], Af[1]);
        sAfb[tid] = __floats2half2_rn(Af[2], Af[3]);
        sAsa[tid] = __floats2half2_rn(As_[0], As_[1]);
        sAsb[tid] = __floats2half2_rn(As_[2], As_[3]);
    }
    if (tid < 32)
        sC[tid] = ((const float4*)(g_cf + (size_t)l * CC))[tid];
    else if (tid < 64)
        sC[tid] = ((const float4*)(g_cs + (size_t)l * CC))[tid - 32];
    __syncthreads();

    int lane = tid & 31;
    int n = (blockIdx.x * 256 + tid) >> 5;
    if (n >= NN) return;

    const float4* T4 = (const float4*)g_T;
    float4 fi = T4[(size_t)n * 128 + lane];
    float4 si = T4[(size_t)n * 128 + 64 + lane];
    float4 c0 = sC[lane], c1 = sC[32 + lane];
    fi.x += c0.x; fi.y += c0.y; fi.z += c0.z; fi.w += c0.w;
    si.x += c1.x; si.y += c1.y; si.z += c1.z; si.w += c1.w;

    float4 mx = make_float4(0.f, 0.f, 0.f, 0.f);
    int beg = g_off[n], end = g_off[n + 1];

    float4 fjn, sjn;
    uint4 ean;
    if (beg < end) {
        int s0 = g_srcs[beg];
        fjn = T4[(size_t)s0 * 128 + 32 + lane];
        sjn = T4[(size_t)s0 * 128 + 96 + lane];
        ean = g_eash[beg];
    }
    for (int j = beg; j < end; j++) {
        float4 fj = fjn, sj = sjn;
        uint4 ea = ean;
        if (j + 1 < end) {
            int s1 = g_srcs[j + 1];
            fjn = T4[(size_t)s1 * 128 + 32 + lane];
            sjn = T4[(size_t)s1 * 128 + 96 + lane];
            ean = g_eash[j + 1];
        }
        half2 p01 = *(half2*)&ea.x;
        half2 p23 = *(half2*)&ea.y;
        half2 p45 = *(half2*)&ea.z;
        half2 a0 = __low2half2(p01), a1 = __high2half2(p01);
        half2 a2 = __low2half2(p23), a3 = __high2half2(p23);
        half2 a4 = __low2half2(p45), a5 = __high2half2(p45);

        half2 fa = __hmul2(a0, sAfa[lane]);
        half2 fb = __hmul2(a0, sAfb[lane]);
        half2 sa = __hmul2(a0, sAsa[lane]);
        half2 sb = __hmul2(a0, sAsb[lane]);
        fa = __hfma2(a1, sAfa[32 + lane], fa);  fb = __hfma2(a1, sAfb[32 + lane], fb);
        sa = __hfma2(a1, sAsa[32 + lane], sa);  sb = __hfma2(a1, sAsb[32 + lane], sb);
        fa = __hfma2(a2, sAfa[64 + lane], fa);  fb = __hfma2(a2, sAfb[64 + lane], fb);
        sa = __hfma2(a2, sAsa[64 + lane], sa);  sb = __hfma2(a2, sAsb[64 + lane], sb);
        fa = __hfma2(a3, sAfa[96 + lane], fa);  fb = __hfma2(a3, sAfb[96 + lane], fb);
        sa = __hfma2(a3, sAsa[96 + lane], sa);  sb = __hfma2(a3, sAsb[96 + lane], sb);
        fa = __hfma2(a4, sAfa[128 + lane], fa); fb = __hfma2(a4, sAfb[128 + lane], fb);
        sa = __hfma2(a4, sAsa[128 + lane], sa); sb = __hfma2(a4, sAsb[128 + lane], sb);
        fa = __hfma2(a5, sAfa[160 + lane], fa); fb = __hfma2(a5, sAfb[160 + lane], fb);
        sa = __hfma2(a5, sAsa[160 + lane], sa); sb = __hfma2(a5, sAsb[160 + lane], sb);

        float2 efa = __half22float2(fa), efb = __half22float2(fb);
        float2 esa = __half22float2(sa), esb = __half22float2(sb);

        float zf0 = (fi.x + fj.x) + efa.x;
        float zf1 = (fi.y + fj.y) + efa.y;
        float zf2 = (fi.z + fj.z) + efb.x;
        float zf3 = (fi.w + fj.w) + efb.y;
        float zs0 = (si.x + sj.x) + esa.x;
        float zs1 = (si.y + sj.y) + esa.y;
        float zs2 = (si.z + sj.z) + esb.x;
        float zs3 = (si.w + sj.w) + esb.y;

        mx.x = fmaxf(mx.x, msg1(zf0, zs0));
        mx.y = fmaxf(mx.y, msg1(zf1, zs1));
        mx.z = fmaxf(mx.z, msg1(zf2, zs2));
        mx.w = fmaxf(mx.w, msg1(zf3, zs3));
    }

    float4 g4 = ((const float4*)(gamma + (size_t)l * CC))[lane];
    float4 b4 = ((const float4*)(beta + (size_t)l * CC))[lane];
    float4 m4 = ((const float4*)(bmean + (size_t)l * CC))[lane];
    float4 v4 = ((const float4*)(bvar + (size_t)l * CC))[lane];
    float4* H4 = (float4*)g_h;
    float4 h4 = H4[(size_t)n * 32 + lane];
    h4.x += (mx.x - m4.x) * rsqrtf(v4.x + 1e-5f) * g4.x + b4.x;
    h4.y += (mx.y - m4.y) * rsqrtf(v4.y + 1e-5f) * g4.y + b4.y;
    h4.z += (mx.z - m4.z) * rsqrtf(v4.z + 1e-5f) * g4.z + b4.z;
    h4.w += (mx.w - m4.w) * rsqrtf(v4.w + 1e-5f) * g4.w + b4.w;
    H4[(size_t)n * 32 + lane] = h4;
}

// ---------------- final head + h copy ----------------
__global__ void __launch_bounds__(256) k_final(const float* __restrict__ linW,
                                               const float* __restrict__ linb,
                                               float* __restrict__ out) {
    int tid = threadIdx.x;
    int lane = tid & 31;
    int n = (blockIdx.x * 256 + tid) >> 5;
    if (n >= NN) return;
    float4 h4 = ((const float4*)g_h)[(size_t)n * 32 + lane];
#pragma unroll
    for (int j = 0; j < KK; j++) {
        float4 w = ((const float4*)linW)[j * 32 + lane];
        float p = h4.x * w.x + h4.y * w.y + h4.z * w.z + h4.w * w.w;
#pragma unroll
        for (int d = 16; d; d >>= 1) p += __shfl_xor_sync(0xffffffffu, p, d);
        if (lane == 0) out[(size_t)n * KK + j] = p + __ldg(linb + j);
    }
    ((float4*)(out + (size_t)NN * KK))[(size_t)n * 32 + lane] = h4;
}

// ---------------- launch ----------------
extern "C" void kernel_launch(void* const* d_in, const int* in_sizes, int n_in,
                              void* d_out, int out_size) {
    const float* x       = (const float*)d_in[0];
    const void*  ei      = d_in[1];
    const float* ea      = (const float*)d_in[2];
    const float* node_W  = (const float*)d_in[3];
    const float* node_b  = (const float*)d_in[4];
    const float* edge_W  = (const float*)d_in[5];
    const float* edge_b  = (const float*)d_in[6];
    const float* Wf      = (const float*)d_in[7];
    const float* bf      = (const float*)d_in[8];
    const float* Ws      = (const float*)d_in[9];
    const float* bs      = (const float*)d_in[10];
    const float* gamma   = (const float*)d_in[11];
    const float* beta    = (const float*)d_in[12];
    const float* bn_mean = (const float*)d_in[13];
    const float* bn_var  = (const float*)d_in[14];
    const float* lin_W   = (const float*)d_in[15];
    const float* lin_b   = (const float*)d_in[16];
    float* out = (float*)d_out;

    cudaFuncSetAttribute(k_mma, cudaFuncAttributeMaxDynamicSharedMemorySize, SMEM_MMA);

    dim3 ggrid((NN + 127) / 128, 4);

    k_detect<<<1, 256>>>((const int*)ei);                                       // 0
    k_setup<<<ZB + FB + WB + NB, 256>>>(x, node_W, node_b, Wf, bf, Ws, bs,
                                        edge_W, edge_b);                        // 1
    k_hist<<<(EE + 255) / 256, 256>>>(ei);                                      // 2
    k_scan1<<<SC_NB, 256>>>();                                                  // 3
    k_scan2<<<1, 32>>>();                                                       // 4
    k_mma<<<ggrid, 256, SMEM_MMA>>>(0);                                         // 5 (profiled)
    k_scan3<<<SC_NB, 256>>>();                                                  // 6
    k_scatter<<<(EE + 255) / 256, 256>>>(ei, ea);                               // 7
    k_agg<<<(NN * 32 + 255) / 256, 256>>>(gamma, beta, bn_mean, bn_var, 0);     // 8

    for (int l = 1; l < LL; l++) {
        k_mma<<<ggrid, 256, SMEM_MMA>>>(l);
        k_agg<<<(NN * 32 + 255) / 256, 256>>>(gamma, beta, bn_mean, bn_var, l);
    }

    k_final<<<(NN * 32 + 255) / 256, 256>>>(lin_W, lin_b, out);
}

// round 5
// speedup vs baseline: 1.8637x; 1.1877x over previous
#include <cuda_runtime.h>
#include <cuda_fp16.h>
#include <cstdint>

#define NN 50000
#define EE 800000
#define CC 128
#define LL 3
#define KK 10

#define LOG2E 1.4426950408889634f
#define LN2   0.6931471805599453f

// ---------------- scratch ----------------
__device__ __align__(16) float  g_h[NN * CC];                 // 25.6 MB
__device__ __align__(16) float  g_Ti[(size_t)NN * 256];       // 51.2 MB: [hf_i | hs_i] (prescaled)
__device__ __align__(16) __half g_Tj[(size_t)NN * 256];       // 25.6 MB: interleaved [hf_j x4 | hs_j x4] per 4-col group
__device__ __align__(16) float  g_Bcat[LL * 512 * CC];        // prescaled weight rows
__device__ __align__(16) float  g_AfT[LL * 6 * CC];           // prescaled (x0.5)
__device__ __align__(16) float  g_AsT[LL * 6 * CC];           // prescaled (xlog2e)
__device__ __align__(16) float  g_cf[LL * CC];                // prescaled
__device__ __align__(16) float  g_cs[LL * CC];                // prescaled
__device__ int   g_deg[NN + 1];
__device__ int   g_off[NN + 1];
__device__ int   g_cur[NN];
__device__ __align__(16) uint4 g_edge[EE];  // {src, ea01, ea23, ea45}
__device__ int   g_bsum[64];
__device__ int   g_is64;

// ---------------- math helpers ----------------
__device__ __forceinline__ float tanh_fast(float x) {
    float r;
    asm("tanh.approx.f32 %0, %1;" : "=f"(r) : "f"(x));
    return r;
}
__device__ __forceinline__ float ex2f(float x) {
    float r;
    asm("ex2.approx.f32 %0, %1;" : "=f"(r) : "f"(x));
    return r;
}
__device__ __forceinline__ float lg2f(float x) {
    float r;
    asm("lg2.approx.f32 %0, %1;" : "=f"(r) : "f"(x));
    return r;
}
// zf prescaled by 0.5, zs prescaled by log2e; returns msg/ln2
__device__ __forceinline__ float msg_s(float zf, float zs) {
    float sg = fmaf(tanh_fast(zf), 0.5f, 0.5f);
    float e = ex2f(-fabsf(zs));
    float sp = fmaxf(zs, 0.f) + lg2f(1.f + e);
    return sg * sp;
}

__device__ __forceinline__ uint32_t f2tf32(float f) {
    uint32_t o;
    asm("cvt.rna.tf32.f32 %0, %1;" : "=r"(o) : "f"(f));
    return o;
}
__device__ __forceinline__ void mma_tf32(float* d, const uint32_t* a, const uint32_t* b) {
    asm volatile(
        "mma.sync.aligned.m16n8k8.row.col.f32.tf32.tf32.f32 "
        "{%0,%1,%2,%3}, {%4,%5,%6,%7}, {%8,%9}, {%0,%1,%2,%3};"
        : "+f"(d[0]), "+f"(d[1]), "+f"(d[2]), "+f"(d[3])
        : "r"(a[0]), "r"(a[1]), "r"(a[2]), "r"(a[3]), "r"(b[0]), "r"(b[1]));
}

// ---------------- detect int32 vs int64 edge_index ----------------
__global__ void k_detect(const int* __restrict__ ei32) {
    __shared__ int any;
    if (threadIdx.x == 0) any = 0;
    __syncthreads();
    for (int i = threadIdx.x; i < 4096; i += blockDim.x)
        if (ei32[2 * i + 1] != 0) any = 1;
    __syncthreads();
    if (threadIdx.x == 0) g_is64 = (any == 0) ? 1 : 0;
}
__device__ __forceinline__ int load_idx(const void* ei, long long pos) {
    if (g_is64) return (int)(((const long long*)ei)[pos]);
    return ((const int*)ei)[pos];
}

// ---------------- fused setup: zero_deg | fold | bprep | node_encode ----------------
#define ZB 196
#define FB 21
#define WB 768
#define NB 25000
__global__ void k_setup(const float* __restrict__ x, const float* __restrict__ nW,
                        const float* __restrict__ nb,
                        const float* __restrict__ Wf, const float* __restrict__ bf,
                        const float* __restrict__ Ws, const float* __restrict__ bs,
                        const float* __restrict__ eW, const float* __restrict__ eb) {
    int b = blockIdx.x, tid = threadIdx.x;
    if (b < ZB) {
        int i = b * 256 + tid;
        if (i <= NN) g_deg[i] = 0;
    } else if (b < ZB + FB) {
        int t = (b - ZB) * 256 + tid;
        if (t >= LL * CC * 14) return;
        int l = t / (CC * 14);
        int r = t % (CC * 14);
        int c = r / 14, kk = r % 14;
        const float* rf = Wf + ((size_t)(l * CC + c) * 3 * CC) + 2 * CC;
        const float* rs = Ws + ((size_t)(l * CC + c) * 3 * CC) + 2 * CC;
        if (kk < 6) {
            float s = 0.f;
            for (int j = 0; j < CC; j++) s = fmaf(rf[j], eW[j * 6 + kk], s);
            g_AfT[l * 6 * CC + kk * CC + c] = s * 0.5f;
        } else if (kk < 12) {
            int k = kk - 6;
            float s = 0.f;
            for (int j = 0; j < CC; j++) s = fmaf(rs[j], eW[j * 6 + k], s);
            g_AsT[l * 6 * CC + k * CC + c] = s * LOG2E;
        } else if (kk == 12) {
            float s = bf[l * CC + c];
            for (int j = 0; j < CC; j++) s = fmaf(rf[j], eb[j], s);
            g_cf[l * CC + c] = s * 0.5f;
        } else {
            float s = bs[l * CC + c];
            for (int j = 0; j < CC; j++) s = fmaf(rs[j], eb[j], s);
            g_cs[l * CC + c] = s * LOG2E;
        }
    } else if (b < ZB + FB + WB) {
        int t = (b - ZB - FB) * 256 + tid;
        int l = t / (512 * CC);
        int r = t % (512 * CC);
        int n = r / CC, k = r % CC;
        int q = n >> 7, c = n & 127;
        const float* base = (q < 2 ? Wf : Ws);
        float scale = (q < 2) ? 0.5f : LOG2E;
        g_Bcat[t] = base[(size_t)(l * CC + c) * 3 * CC + ((q & 1) ? CC : 0) + k] * scale;
    } else {
        int i = (b - ZB - FB - WB) * 256 + tid;
        int n = i / CC, c = i % CC;
        const float* xr = x + (size_t)n * 7;
        const float* wr = nW + (size_t)c * 7;
        float acc = nb[c];
#pragma unroll
        for (int k = 0; k < 7; k++) acc = fmaf(xr[k], wr[k], acc);
        g_h[i] = acc;
    }
}

// ---------------- CSR build ----------------
__global__ void k_hist(const void* __restrict__ ei) {
    int e = blockIdx.x * blockDim.x + threadIdx.x;
    if (e >= EE) return;
    atomicAdd(&g_deg[load_idx(ei, (long long)EE + e)], 1);
}

#define SC_NB 50
__global__ void __launch_bounds__(256) k_scan1() {
    __shared__ int sw[8];
    int b = blockIdx.x, tid = threadIdx.x, lane = tid & 31, wid = tid >> 5;
    int base = b * 1024 + tid * 4;
    int v[4];
    int run = 0;
#pragma unroll
    for (int i = 0; i < 4; i++) {
        int idx = base + i;
        int t = (idx <= NN) ? g_deg[idx] : 0;
        v[i] = run;
        run += t;
    }
    int incl = run;
#pragma unroll
    for (int d = 1; d < 32; d <<= 1) {
        int y = __shfl_up_sync(0xffffffffu, incl, d);
        if (lane >= d) incl += y;
    }
    if (lane == 31) sw[wid] = incl;
    __syncthreads();
    if (tid < 8) {
        int w = sw[tid];
        int wi = w;
#pragma unroll
        for (int d = 1; d < 8; d <<= 1) {
            int y = __shfl_up_sync(0xffu, wi, d);
            if (tid >= d) wi += y;
        }
        sw[tid] = wi - w;
        if (tid == 7) g_bsum[b] = wi;
    }
    __syncthreads();
    int off0 = sw[wid] + (incl - run);
#pragma unroll
    for (int i = 0; i < 4; i++) {
        int idx = base + i;
        if (idx <= NN) g_off[idx] = off0 + v[i];
    }
}

__global__ void k_scan2() {
    int lane = threadIdx.x;  // 32
    int e0 = (2 * lane < SC_NB) ? g_bsum[2 * lane] : 0;
    int e1 = (2 * lane + 1 < SC_NB) ? g_bsum[2 * lane + 1] : 0;
    int s = e0 + e1;
    int incl = s;
#pragma unroll
    for (int d = 1; d < 32; d <<= 1) {
        int y = __shfl_up_sync(0xffffffffu, incl, d);
        if (lane >= d) incl += y;
    }
    int excl = incl - s;
    if (2 * lane < SC_NB) g_bsum[2 * lane] = excl;
    if (2 * lane + 1 < SC_NB) g_bsum[2 * lane + 1] = excl + e0;
}

__global__ void __launch_bounds__(256) k_scan3() {
    int b = blockIdx.x, tid = threadIdx.x;
    int add = g_bsum[b];
#pragma unroll
    for (int i = 0; i < 4; i++) {
        int idx = b * 1024 + tid * 4 + i;
        if (idx <= NN) {
            int o = g_off[idx] + add;
            g_off[idx] = o;
            if (idx < NN) g_cur[idx] = o;
        }
    }
}

__global__ void k_scatter(const void* __restrict__ ei, const float* __restrict__ ea) {
    int e = blockIdx.x * blockDim.x + threadIdx.x;
    if (e >= EE) return;
    int dst = load_idx(ei, (long long)EE + e);
    int src = load_idx(ei, e);
    int pos = atomicAdd(&g_cur[dst], 1);
    const float* a = ea + (size_t)e * 6;
    half2 x01 = __floats2half2_rn(a[0], a[1]);
    half2 x23 = __floats2half2_rn(a[2], a[3]);
    half2 x45 = __floats2half2_rn(a[4], a[5]);
    uint4 u;
    u.x = (uint32_t)src;
    u.y = *(uint32_t*)&x01;
    u.z = *(uint32_t*)&x23;
    u.w = *(uint32_t*)&x45;
    g_edge[pos] = u;
}

// ---------------- mma.sync tf32 GEMM: T = h @ Bcat^T (M=NN, N=512, K=128) ----------------
#define LDA 132
#define SMEM_MMA (2 * 128 * LDA * 4)

__global__ void __launch_bounds__(256) k_mma(int l) {
    extern __shared__ uint32_t smem_u[];
    uint32_t* sA = smem_u;
    uint32_t* sB = smem_u + 128 * LDA;
    const int tid = threadIdx.x;
    const int wid = tid >> 5, lane = tid & 31;
    const int bm = blockIdx.x * 128;
    const int q = blockIdx.y;  // 0:hf_i 1:hf_j 2:hs_i 3:hs_j

#pragma unroll
    for (int i = 0; i < 16; i++) {
        int idx = tid + i * 256;
        int row = idx >> 5;
        int col = (idx & 31) << 2;
        float4 v = make_float4(0.f, 0.f, 0.f, 0.f);
        if (bm + row < NN) v = *(const float4*)(g_h + (size_t)(bm + row) * CC + col);
        uint32_t* d = sA + row * LDA + col;
        d[0] = f2tf32(v.x); d[1] = f2tf32(v.y); d[2] = f2tf32(v.z); d[3] = f2tf32(v.w);
    }
    const float* Bsrc = g_Bcat + ((size_t)l * 512 + q * 128) * CC;
#pragma unroll
    for (int i = 0; i < 16; i++) {
        int idx = tid + i * 256;
        int row = idx >> 5;
        int col = (idx & 31) << 2;
        float4 v = *(const float4*)(Bsrc + (size_t)row * CC + col);
        uint32_t* d = sB + row * LDA + col;
        d[0] = f2tf32(v.x); d[1] = f2tf32(v.y); d[2] = f2tf32(v.z); d[3] = f2tf32(v.w);
    }
    __syncthreads();

    const int wm = (wid >> 1) * 32;
    const int wn = (wid & 1) * 64;
    const int gr = lane >> 2;
    const int tg = lane & 3;

    float acc[2][8][4];
#pragma unroll
    for (int mi = 0; mi < 2; mi++)
#pragma unroll
        for (int ni = 0; ni < 8; ni++)
#pragma unroll
            for (int p = 0; p < 4; p++) acc[mi][ni][p] = 0.f;

#pragma unroll
    for (int ks = 0; ks < 16; ks++) {
        const int k0 = ks * 8;
        uint32_t a[2][4];
#pragma unroll
        for (int mi = 0; mi < 2; mi++) {
            const uint32_t* ap = sA + (wm + mi * 16 + gr) * LDA + k0 + tg;
            a[mi][0] = ap[0];
            a[mi][1] = ap[8 * LDA];
            a[mi][2] = ap[4];
            a[mi][3] = ap[8 * LDA + 4];
        }
        uint32_t b[8][2];
#pragma unroll
        for (int ni = 0; ni < 8; ni++) {
            const uint32_t* bp = sB + (wn + ni * 8 + gr) * LDA + k0 + tg;
            b[ni][0] = bp[0];
            b[ni][1] = bp[4];
        }
#pragma unroll
        for (int mi = 0; mi < 2; mi++)
#pragma unroll
            for (int ni = 0; ni < 8; ni++)
                mma_tf32(acc[mi][ni], a[mi], b[ni]);
    }

    // epilogue: q even -> f32 into g_Ti; q odd -> half2 interleaved into g_Tj
    if ((q & 1) == 0) {
        const int cb = (q >> 1) * 128;
#pragma unroll
        for (int mi = 0; mi < 2; mi++) {
            int r0 = bm + wm + mi * 16 + gr;
            int r1 = r0 + 8;
#pragma unroll
            for (int ni = 0; ni < 8; ni++) {
                int lc = wn + ni * 8 + tg * 2;
                if (r0 < NN) *(float2*)(g_Ti + (size_t)r0 * 256 + cb + lc) = make_float2(acc[mi][ni][0], acc[mi][ni][1]);
                if (r1 < NN) *(float2*)(g_Ti + (size_t)r1 * 256 + cb + lc) = make_float2(acc[mi][ni][2], acc[mi][ni][3]);
            }
        }
    } else {
        const int add = (q == 3) ? 4 : 0;
#pragma unroll
        for (int mi = 0; mi < 2; mi++) {
            int r0 = bm + wm + mi * 16 + gr;
            int r1 = r0 + 8;
#pragma unroll
            for (int ni = 0; ni < 8; ni++) {
                int lc = wn + ni * 8 + tg * 2;
                int i0 = ((lc >> 2) << 3) + (lc & 3) + add;
                if (r0 < NN) *(__half2*)(g_Tj + (size_t)r0 * 256 + i0) = __floats2half2_rn(acc[mi][ni][0], acc[mi][ni][1]);
                if (r1 < NN) *(__half2*)(g_Tj + (size_t)r1 * 256 + i0) = __floats2half2_rn(acc[mi][ni][2], acc[mi][ni][3]);
            }
        }
    }
}

// ---------------- per-layer aggregation (CSR gather-max) + BN + residual ----------------
__global__ void __launch_bounds__(256) k_agg(const float* __restrict__ gamma,
                                             const float* __restrict__ beta,
                                             const float* __restrict__ bmean,
                                             const float* __restrict__ bvar,
                                             int l) {
    __shared__ half2 sAfa[192], sAfb[192], sAsa[192], sAsb[192];
    __shared__ float4 sC[64];
    int tid = threadIdx.x;
    if (tid < 192) {
        int k = tid >> 5, ln = tid & 31;
        const float* Af = g_AfT + (size_t)l * 6 * CC + k * CC + 4 * ln;
        const float* As_ = g_AsT + (size_t)l * 6 * CC + k * CC + 4 * ln;
        sAfa[tid] = __floats2half2_rn(Af[0], Af[1]);
        sAfb[tid] = __floats2half2_rn(Af[2], Af[3]);
        sAsa[tid] = __floats2half2_rn(As_[0], As_[1]);
        sAsb[tid] = __floats2half2_rn(As_[2], As_[3]);
    }
    if (tid < 32)
        sC[tid] = ((const float4*)(g_cf + (size_t)l * CC))[tid];
    else if (tid < 64)
        sC[tid] = ((const float4*)(g_cs + (size_t)l * CC))[tid - 32];
    __syncthreads();

    int lane = tid & 31;
    int n = (blockIdx.x * 256 + tid) >> 5;
    if (n >= NN) return;

    const float4* Ti4 = (const float4*)g_Ti;
    float4 fi = Ti4[(size_t)n * 64 + lane];        // hf_i (prescaled x0.5)
    float4 si = Ti4[(size_t)n * 64 + 32 + lane];   // hs_i (prescaled xlog2e)
    float4 c0 = sC[lane], c1 = sC[32 + lane];
    fi.x += c0.x; fi.y += c0.y; fi.z += c0.z; fi.w += c0.w;
    si.x += c1.x; si.y += c1.y; si.z += c1.z; si.w += c1.w;

    const uint4* Tj4 = (const uint4*)g_Tj;  // row stride 32 uint4

    float4 mx = make_float4(0.f, 0.f, 0.f, 0.f);
    int beg = g_off[n], end = g_off[n + 1];

    uint4 e0, e1, tj0;
    if (beg < end) {
        e0 = g_edge[beg];
        tj0 = Tj4[(size_t)e0.x * 32 + lane];
    }
    if (beg + 1 < end) e1 = g_edge[beg + 1];

    for (int j = beg; j < end; j++) {
        uint4 ec = e0;
        uint4 tj = tj0;
        if (j + 1 < end) {
            tj0 = Tj4[(size_t)e1.x * 32 + lane];
            e0 = e1;
        }
        if (j + 2 < end) e1 = g_edge[j + 2];

        half2 p01 = *(half2*)&ec.y;
        half2 p23 = *(half2*)&ec.z;
        half2 p45 = *(half2*)&ec.w;
        half2 a0 = __low2half2(p01), a1 = __high2half2(p01);
        half2 a2 = __low2half2(p23), a3 = __high2half2(p23);
        half2 a4 = __low2half2(p45), a5 = __high2half2(p45);

        half2 fa = __hmul2(a0, sAfa[lane]);
        half2 fb = __hmul2(a0, sAfb[lane]);
        half2 sa = __hmul2(a0, sAsa[lane]);
        half2 sb = __hmul2(a0, sAsb[lane]);
        fa = __hfma2(a1, sAfa[32 + lane], fa);  fb = __hfma2(a1, sAfb[32 + lane], fb);
        sa = __hfma2(a1, sAsa[32 + lane], sa);  sb = __hfma2(a1, sAsb[32 + lane], sb);
        fa = __hfma2(a2, sAfa[64 + lane], fa);  fb = __hfma2(a2, sAfb[64 + lane], fb);
        sa = __hfma2(a2, sAsa[64 + lane], sa);  sb = __hfma2(a2, sAsb[64 + lane], sb);
        fa = __hfma2(a3, sAfa[96 + lane], fa);  fb = __hfma2(a3, sAfb[96 + lane], fb);
        sa = __hfma2(a3, sAsa[96 + lane], sa);  sb = __hfma2(a3, sAsb[96 + lane], sb);
        fa = __hfma2(a4, sAfa[128 + lane], fa); fb = __hfma2(a4, sAfb[128 + lane], fb);
        sa = __hfma2(a4, sAsa[128 + lane], sa); sb = __hfma2(a4, sAsb[128 + lane], sb);
        fa = __hfma2(a5, sAfa[160 + lane], fa); fb = __hfma2(a5, sAfb[160 + lane], fb);
        sa = __hfma2(a5, sAsa[160 + lane], sa); sb = __hfma2(a5, sAsb[160 + lane], sb);

        // add fj/sj halves (tj: x=hf01 y=hf23 z=hs01 w=hs23)
        fa = __hadd2(fa, *(half2*)&tj.x);
        fb = __hadd2(fb, *(half2*)&tj.y);
        sa = __hadd2(sa, *(half2*)&tj.z);
        sb = __hadd2(sb, *(half2*)&tj.w);

        float2 efa = __half22float2(fa), efb = __half22float2(fb);
        float2 esa = __half22float2(sa), esb = __half22float2(sb);

        mx.x = fmaxf(mx.x, msg_s(fi.x + efa.x, si.x + esa.x));
        mx.y = fmaxf(mx.y, msg_s(fi.y + efa.y, si.y + esa.y));
        mx.z = fmaxf(mx.z, msg_s(fi.z + efb.x, si.z + esb.x));
        mx.w = fmaxf(mx.w, msg_s(fi.w + efb.y, si.w + esb.y));
    }

    float4 g4 = ((const float4*)(gamma + (size_t)l * CC))[lane];
    float4 b4 = ((const float4*)(beta + (size_t)l * CC))[lane];
    float4 m4 = ((const float4*)(bmean + (size_t)l * CC))[lane];
    float4 v4 = ((const float4*)(bvar + (size_t)l * CC))[lane];
    float4* H4 = (float4*)g_h;
    float4 h4 = H4[(size_t)n * 32 + lane];
    h4.x += (mx.x * LN2 - m4.x) * rsqrtf(v4.x + 1e-5f) * g4.x + b4.x;
    h4.y += (mx.y * LN2 - m4.y) * rsqrtf(v4.y + 1e-5f) * g4.y + b4.y;
    h4.z += (mx.z * LN2 - m4.z) * rsqrtf(v4.z + 1e-5f) * g4.z + b4.z;
    h4.w += (mx.w * LN2 - m4.w) * rsqrtf(v4.w + 1e-5f) * g4.w + b4.w;
    H4[(size_t)n * 32 + lane] = h4;
}

// ---------------- final head + h copy ----------------
__global__ void __launch_bounds__(256) k_final(const float* __restrict__ linW,
                                               const float* __restrict__ linb,
                                               float* __restrict__ out) {
    int tid = threadIdx.x;
    int lane = tid & 31;
    int n = (blockIdx.x * 256 + tid) >> 5;
    if (n >= NN) return;
    float4 h4 = ((const float4*)g_h)[(size_t)n * 32 + lane];
#pragma unroll
    for (int j = 0; j < KK; j++) {
        float4 w = ((const float4*)linW)[j * 32 + lane];
        float p = h4.x * w.x + h4.y * w.y + h4.z * w.z + h4.w * w.w;
#pragma unroll
        for (int d = 16; d; d >>= 1) p += __shfl_xor_sync(0xffffffffu, p, d);
        if (lane == 0) out[(size_t)n * KK + j] = p + __ldg(linb + j);
    }
    ((float4*)(out + (size_t)NN * KK))[(size_t)n * 32 + lane] = h4;
}

// ---------------- launch ----------------
extern "C" void kernel_launch(void* const* d_in, const int* in_sizes, int n_in,
                              void* d_out, int out_size) {
    const float* x       = (const float*)d_in[0];
    const void*  ei      = d_in[1];
    const float* ea      = (const float*)d_in[2];
    const float* node_W  = (const float*)d_in[3];
    const float* node_b  = (const float*)d_in[4];
    const float* edge_W  = (const float*)d_in[5];
    const float* edge_b  = (const float*)d_in[6];
    const float* Wf      = (const float*)d_in[7];
    const float* bf      = (const float*)d_in[8];
    const float* Ws      = (const float*)d_in[9];
    const float* bs      = (const float*)d_in[10];
    const float* gamma   = (const float*)d_in[11];
    const float* beta    = (const float*)d_in[12];
    const float* bn_mean = (const float*)d_in[13];
    const float* bn_var  = (const float*)d_in[14];
    const float* lin_W   = (const float*)d_in[15];
    const float* lin_b   = (const float*)d_in[16];
    float* out = (float*)d_out;

    cudaFuncSetAttribute(k_mma, cudaFuncAttributeMaxDynamicSharedMemorySize, SMEM_MMA);

    dim3 ggrid((NN + 127) / 128, 4);

    k_detect<<<1, 256>>>((const int*)ei);                                       // 0
    k_setup<<<ZB + FB + WB + NB, 256>>>(x, node_W, node_b, Wf, bf, Ws, bs,
                                        edge_W, edge_b);                        // 1
    k_hist<<<(EE + 255) / 256, 256>>>(ei);                                      // 2
    k_scan1<<<SC_NB, 256>>>();                                                  // 3
    k_scan2<<<1, 32>>>();                                                       // 4
    k_mma<<<ggrid, 256, SMEM_MMA>>>(0);                                         // 5
    k_scan3<<<SC_NB, 256>>>();                                                  // 6
    k_scatter<<<(EE + 255) / 256, 256>>>(ei, ea);                               // 7
    k_agg<<<(NN * 32 + 255) / 256, 256>>>(gamma, beta, bn_mean, bn_var, 0);     // 8

    for (int l = 1; l < LL; l++) {
        k_mma<<<ggrid, 256, SMEM_MMA>>>(l);
        k_agg<<<(NN * 32 + 255) / 256, 256>>>(gamma, beta, bn_mean, bn_var, l);
    }

    k_final<<<(NN * 32 + 255) / 256, 256>>>(lin_W, lin_b, out);
}

// round 7
// speedup vs baseline: 1.9913x; 1.0685x over previous
#include <cuda_runtime.h>
#include <cuda_fp16.h>
#include <cstdint>

#define NN 50000
#define EE 800000
#define CC 128
#define LL 3
#define KK 10

#define LOG2E 1.4426950408889634f
#define LN2   0.6931471805599453f
#define MSCALE 0.34657359027997264f  // 0.5 * ln2

// ---------------- scratch ----------------
__device__ __align__(16) float  g_h[NN * CC];                 // 25.6 MB
__device__ __align__(16) float  g_Ti[(size_t)NN * 256];       // [hf_i | hs_i] (prescaled)
__device__ __align__(16) __half g_Tj[(size_t)NN * 256];       // interleaved [hf_j x4 | hs_j x4]
__device__ __align__(16) float  g_Bcat[LL * 512 * CC];        // prescaled weight rows
__device__ __align__(16) float  g_AfT[LL * 6 * CC];           // x0.5
__device__ __align__(16) float  g_AsT[LL * 6 * CC];           // xlog2e
__device__ __align__(16) float  g_cf[LL * CC];
__device__ __align__(16) float  g_cs[LL * CC];
__device__ int   g_deg[NN + 1];
__device__ int   g_off[NN + 1];
__device__ int   g_cur[NN];
__device__ __align__(16) uint4 g_edge[EE];  // {src, ea01, ea23, ea45}
__device__ int   g_bsum[64];

// ---------------- math helpers ----------------
__device__ __forceinline__ float ex2f(float x) {
    float r; asm("ex2.approx.f32 %0, %1;" : "=f"(r) : "f"(x)); return r;
}
__device__ __forceinline__ float lg2f(float x) {
    float r; asm("lg2.approx.f32 %0, %1;" : "=f"(r) : "f"(x)); return r;
}
__device__ __forceinline__ half2 h2tanh_(half2 x) {
    uint32_t xi = *(uint32_t*)&x, ri;
    asm("tanh.approx.f16x2 %0, %1;" : "=r"(ri) : "r"(xi));
    return *(half2*)&ri;
}
// softplus/ln2 on prescaled zs (x log2e already applied upstream)
__device__ __forceinline__ float sp2f(float z) {
    float e = ex2f(-fabsf(z));
    return fmaxf(z, 0.f) + lg2f(1.f + e);
}

__device__ __forceinline__ uint32_t f2tf32(float f) {
    uint32_t o; asm("cvt.rna.tf32.f32 %0, %1;" : "=r"(o) : "f"(f)); return o;
}
__device__ __forceinline__ void mma_tf32(float* d, const uint32_t* a, const uint32_t* b) {
    asm volatile(
        "mma.sync.aligned.m16n8k8.row.col.f32.tf32.tf32.f32 "
        "{%0,%1,%2,%3}, {%4,%5,%6,%7}, {%8,%9}, {%0,%1,%2,%3};"
        : "+f"(d[0]), "+f"(d[1]), "+f"(d[2]), "+f"(d[3])
        : "r"(a[0]), "r"(a[1]), "r"(a[2]), "r"(a[3]), "r"(b[0]), "r"(b[1]));
}

// ---------------- fused setup: zero_deg | fold | bprep | node_encode ----------------
#define ZB 196
#define FB 21
#define WB 768
#define NB 25000
__global__ void k_setup(const float* __restrict__ x, const float* __restrict__ nW,
                        const float* __restrict__ nb,
                        const float* __restrict__ Wf, const float* __restrict__ bf,
                        const float* __restrict__ Ws, const float* __restrict__ bs,
                        const float* __restrict__ eW, const float* __restrict__ eb) {
    int b = blockIdx.x, tid = threadIdx.x;
    if (b < ZB) {
        int i = b * 256 + tid;
        if (i <= NN) g_deg[i] = 0;
    } else if (b < ZB + FB) {
        int t = (b - ZB) * 256 + tid;
        if (t >= LL * CC * 14) return;
        int l = t / (CC * 14);
        int r = t % (CC * 14);
        int c = r / 14, kk = r % 14;
        const float* rf = Wf + ((size_t)(l * CC + c) * 3 * CC) + 2 * CC;
        const float* rs = Ws + ((size_t)(l * CC + c) * 3 * CC) + 2 * CC;
        if (kk < 6) {
            float s = 0.f;
            for (int j = 0; j < CC; j++) s = fmaf(rf[j], eW[j * 6 + kk], s);
            g_AfT[l * 6 * CC + kk * CC + c] = s * 0.5f;
        } else if (kk < 12) {
            int k = kk - 6;
            float s = 0.f;
            for (int j = 0; j < CC; j++) s = fmaf(rs[j], eW[j * 6 + k], s);
            g_AsT[l * 6 * CC + k * CC + c] = s * LOG2E;
        } else if (kk == 12) {
            float s = bf[l * CC + c];
            for (int j = 0; j < CC; j++) s = fmaf(rf[j], eb[j], s);
            g_cf[l * CC + c] = s * 0.5f;
        } else {
            float s = bs[l * CC + c];
            for (int j = 0; j < CC; j++) s = fmaf(rs[j], eb[j], s);
            g_cs[l * CC + c] = s * LOG2E;
        }
    } else if (b < ZB + FB + WB) {
        int t = (b - ZB - FB) * 256 + tid;
        int l = t / (512 * CC);
        int r = t % (512 * CC);
        int n = r / CC, k = r % CC;
        int q = n >> 7, c = n & 127;
        const float* base = (q < 2 ? Wf : Ws);
        float scale = (q < 2) ? 0.5f : LOG2E;
        g_Bcat[t] = base[(size_t)(l * CC + c) * 3 * CC + ((q & 1) ? CC : 0) + k] * scale;
    } else {
        int i = (b - ZB - FB - WB) * 256 + tid;
        int n = i / CC, c = i % CC;
        const float* xr = x + (size_t)n * 7;
        const float* wr = nW + (size_t)c * 7;
        float acc = nb[c];
#pragma unroll
        for (int k = 0; k < 7; k++) acc = fmaf(xr[k], wr[k], acc);
        g_h[i] = acc;
    }
}

// ---------------- CSR build (per-block int32/int64 self-detect) ----------------
__global__ void k_hist(const int* __restrict__ ei32) {
    int e = blockIdx.x * blockDim.x + threadIdx.x;
    int hi = (e < EE) ? ei32[2 * e + 1] : 0;   // src hi-words under int64; arbitrary vals under int32
    int any32 = __syncthreads_or(hi != 0);
    if (e >= EE) return;
    int dst;
    if (any32) dst = ei32[EE + e];
    else       dst = (int)(((const long long*)ei32)[EE + e]);
    atomicAdd(&g_deg[dst], 1);
}

#define SC_NB 50
__global__ void __launch_bounds__(256) k_scan1() {
    __shared__ int sw[8];
    int b = blockIdx.x, tid = threadIdx.x, lane = tid & 31, wid = tid >> 5;
    int base = b * 1024 + tid * 4;
    int v[4];
    int run = 0;
#pragma unroll
    for (int i = 0; i < 4; i++) {
        int idx = base + i;
        int t = (idx <= NN) ? g_deg[idx] : 0;
        v[i] = run;
        run += t;
    }
    int incl = run;
#pragma unroll
    for (int d = 1; d < 32; d <<= 1) {
        int y = __shfl_up_sync(0xffffffffu, incl, d);
        if (lane >= d) incl += y;
    }
    if (lane == 31) sw[wid] = incl;
    __syncthreads();
    if (tid < 8) {
        int w = sw[tid];
        int wi = w;
#pragma unroll
        for (int d = 1; d < 8; d <<= 1) {
            int y = __shfl_up_sync(0xffu, wi, d);
            if (tid >= d) wi += y;
        }
        sw[tid] = wi - w;
        if (tid == 7) g_bsum[b] = wi;
    }
    __syncthreads();
    int off0 = sw[wid] + (incl - run);
#pragma unroll
    for (int i = 0; i < 4; i++) {
        int idx = base + i;
        if (idx <= NN) g_off[idx] = off0 + v[i];
    }
}

__global__ void k_scan2() {
    int lane = threadIdx.x;  // 32
    int e0 = (2 * lane < SC_NB) ? g_bsum[2 * lane] : 0;
    int e1 = (2 * lane + 1 < SC_NB) ? g_bsum[2 * lane + 1] : 0;
    int s = e0 + e1;
    int incl = s;
#pragma unroll
    for (int d = 1; d < 32; d <<= 1) {
        int y = __shfl_up_sync(0xffffffffu, incl, d);
        if (lane >= d) incl += y;
    }
    int excl = incl - s;
    if (2 * lane < SC_NB) g_bsum[2 * lane] = excl;
    if (2 * lane + 1 < SC_NB) g_bsum[2 * lane + 1] = excl + e0;
}

__global__ void __launch_bounds__(256) k_scan3() {
    int b = blockIdx.x, tid = threadIdx.x;
    int add = g_bsum[b];
#pragma unroll
    for (int i = 0; i < 4; i++) {
        int idx = b * 1024 + tid * 4 + i;
        if (idx <= NN) {
            int o = g_off[idx] + add;
            g_off[idx] = o;
            if (idx < NN) g_cur[idx] = o;
        }
    }
}

__global__ void k_scatter(const int* __restrict__ ei32, const float* __restrict__ ea) {
    int e = blockIdx.x * blockDim.x + threadIdx.x;
    int hi = (e < EE) ? ei32[2 * e + 1] : 0;
    int any32 = __syncthreads_or(hi != 0);
    if (e >= EE) return;
    int src, dst;
    if (any32) {
        src = ei32[e];
        dst = ei32[EE + e];
    } else {
        const long long* ll = (const long long*)ei32;
        src = (int)ll[e];
        dst = (int)ll[EE + e];
    }
    int pos = atomicAdd(&g_cur[dst], 1);
    const float* a = ea + (size_t)e * 6;
    half2 x01 = __floats2half2_rn(a[0], a[1]);
    half2 x23 = __floats2half2_rn(a[2], a[3]);
    half2 x45 = __floats2half2_rn(a[4], a[5]);
    uint4 u;
    u.x = (uint32_t)src;
    u.y = *(uint32_t*)&x01;
    u.z = *(uint32_t*)&x23;
    u.w = *(uint32_t*)&x45;
    g_edge[pos] = u;
}

// ---------------- mma.sync tf32 GEMM: T = h @ Bcat^T (M=NN, N=512, K=128) ----------------
#define LDA 132
#define SMEM_MMA (2 * 128 * LDA * 4)

__global__ void __launch_bounds__(256) k_mma(int l) {
    extern __shared__ uint32_t smem_u[];
    uint32_t* sA = smem_u;
    uint32_t* sB = smem_u + 128 * LDA;
    const int tid = threadIdx.x;
    const int wid = tid >> 5, lane = tid & 31;
    const int bm = blockIdx.x * 128;
    const int q = blockIdx.y;  // 0:hf_i 1:hf_j 2:hs_i 3:hs_j

#pragma unroll
    for (int i = 0; i < 16; i++) {
        int idx = tid + i * 256;
        int row = idx >> 5;
        int col = (idx & 31) << 2;
        float4 v = make_float4(0.f, 0.f, 0.f, 0.f);
        if (bm + row < NN) v = *(const float4*)(g_h + (size_t)(bm + row) * CC + col);
        uint32_t* d = sA + row * LDA + col;
        d[0] = f2tf32(v.x); d[1] = f2tf32(v.y); d[2] = f2tf32(v.z); d[3] = f2tf32(v.w);
    }
    const float* Bsrc = g_Bcat + ((size_t)l * 512 + q * 128) * CC;
#pragma unroll
    for (int i = 0; i < 16; i++) {
        int idx = tid + i * 256;
        int row = idx >> 5;
        int col = (idx & 31) << 2;
        float4 v = *(const float4*)(Bsrc + (size_t)row * CC + col);
        uint32_t* d = sB + row * LDA + col;
        d[0] = f2tf32(v.x); d[1] = f2tf32(v.y); d[2] = f2tf32(v.z); d[3] = f2tf32(v.w);
    }
    __syncthreads();

    const int wm = (wid >> 1) * 32;
    const int wn = (wid & 1) * 64;
    const int gr = lane >> 2;
    const int tg = lane & 3;

    float acc[2][8][4];
#pragma unroll
    for (int mi = 0; mi < 2; mi++)
#pragma unroll
        for (int ni = 0; ni < 8; ni++)
#pragma unroll
            for (int p = 0; p < 4; p++) acc[mi][ni][p] = 0.f;

#pragma unroll
    for (int ks = 0; ks < 16; ks++) {
        const int k0 = ks * 8;
        uint32_t a[2][4];
#pragma unroll
        for (int mi = 0; mi < 2; mi++) {
            const uint32_t* ap = sA + (wm + mi * 16 + gr) * LDA + k0 + tg;
            a[mi][0] = ap[0];
            a[mi][1] = ap[8 * LDA];
            a[mi][2] = ap[4];
            a[mi][3] = ap[8 * LDA + 4];
        }
        uint32_t b[8][2];
#pragma unroll
        for (int ni = 0; ni < 8; ni++) {
            const uint32_t* bp = sB + (wn + ni * 8 + gr) * LDA + k0 + tg;
            b[ni][0] = bp[0];
            b[ni][1] = bp[4];
        }
#pragma unroll
        for (int mi = 0; mi < 2; mi++)
#pragma unroll
            for (int ni = 0; ni < 8; ni++)
                mma_tf32(acc[mi][ni], a[mi], b[ni]);
    }

    if ((q & 1) == 0) {
        const int cb = (q >> 1) * 128;
#pragma unroll
        for (int mi = 0; mi < 2; mi++) {
            int r0 = bm + wm + mi * 16 + gr;
            int r1 = r0 + 8;
#pragma unroll
            for (int ni = 0; ni < 8; ni++) {
                int lc = wn + ni * 8 + tg * 2;
                if (r0 < NN) *(float2*)(g_Ti + (size_t)r0 * 256 + cb + lc) = make_float2(acc[mi][ni][0], acc[mi][ni][1]);
                if (r1 < NN) *(float2*)(g_Ti + (size_t)r1 * 256 + cb + lc) = make_float2(acc[mi][ni][2], acc[mi][ni][3]);
            }
        }
    } else {
        const int add = (q == 3) ? 4 : 0;
#pragma unroll
        for (int mi = 0; mi < 2; mi++) {
            int r0 = bm + wm + mi * 16 + gr;
            int r1 = r0 + 8;
#pragma unroll
            for (int ni = 0; ni < 8; ni++) {
                int lc = wn + ni * 8 + tg * 2;
                int i0 = ((lc >> 2) << 3) + (lc & 3) + add;
                if (r0 < NN) *(__half2*)(g_Tj + (size_t)r0 * 256 + i0) = __floats2half2_rn(acc[mi][ni][0], acc[mi][ni][1]);
                if (r1 < NN) *(__half2*)(g_Tj + (size_t)r1 * 256 + i0) = __floats2half2_rn(acc[mi][ni][2], acc[mi][ni][3]);
            }
        }
    }
}

// ---------------- per-layer aggregation (CSR gather-max) + BN + residual ----------------
__global__ void __launch_bounds__(256) k_agg(const float* __restrict__ gamma,
                                             const float* __restrict__ beta,
                                             const float* __restrict__ bmean,
                                             const float* __restrict__ bvar,
                                             int l) {
    __shared__ half2 sAfa[192], sAfb[192], sAsa[192], sAsb[192];
    __shared__ float4 sC[64];
    int tid = threadIdx.x;
    if (tid < 192) {
        int k = tid >> 5, ln = tid & 31;
        const float* Af = g_AfT + (size_t)l * 6 * CC + k * CC + 4 * ln;
        const float* As_ = g_AsT + (size_t)l * 6 * CC + k * CC + 4 * ln;
        sAfa[tid] = __floats2half2_rn(Af[0], Af[1]);
        sAfb[tid] = __floats2half2_rn(Af[2], Af[3]);
        sAsa[tid] = __floats2half2_rn(As_[0], As_[1]);
        sAsb[tid] = __floats2half2_rn(As_[2], As_[3]);
    }
    if (tid < 32)
        sC[tid] = ((const float4*)(g_cf + (size_t)l * CC))[tid];
    else if (tid < 64)
        sC[tid] = ((const float4*)(g_cs + (size_t)l * CC))[tid - 32];
    __syncthreads();

    int lane = tid & 31;
    int n = (blockIdx.x * 256 + tid) >> 5;
    if (n >= NN) return;

    const float4* Ti4 = (const float4*)g_Ti;
    float4 fi = Ti4[(size_t)n * 64 + lane];        // hf_i (x0.5)
    float4 si = Ti4[(size_t)n * 64 + 32 + lane];   // hs_i (xlog2e)
    float4 c0 = sC[lane], c1 = sC[32 + lane];
    fi.x += c0.x; fi.y += c0.y; fi.z += c0.z; fi.w += c0.w;
    si.x += c1.x; si.y += c1.y; si.z += c1.z; si.w += c1.w;
    half2 fi2a = __floats2half2_rn(fi.x, fi.y);
    half2 fi2b = __floats2half2_rn(fi.z, fi.w);

    const uint4* Tj4 = (const uint4*)g_Tj;

    half2 mx0 = __floats2half2_rn(0.f, 0.f);
    half2 mx1 = mx0;
    int beg = g_off[n], end = g_off[n + 1];

    uint4 e0, e1, tj0;
    if (beg < end) {
        e0 = g_edge[beg];
        tj0 = Tj4[(size_t)e0.x * 32 + lane];
    }
    if (beg + 1 < end) e1 = g_edge[beg + 1];

    for (int j = beg; j < end; j++) {
        uint4 ec = e0;
        uint4 tj = tj0;
        if (j + 1 < end) {
            tj0 = Tj4[(size_t)e1.x * 32 + lane];
            e0 = e1;
        }
        if (j + 2 < end) e1 = g_edge[j + 2];

        half2 p01 = *(half2*)&ec.y;
        half2 p23 = *(half2*)&ec.z;
        half2 p45 = *(half2*)&ec.w;
        half2 a0 = __low2half2(p01), a1 = __high2half2(p01);
        half2 a2 = __low2half2(p23), a3 = __high2half2(p23);
        half2 a4 = __low2half2(p45), a5 = __high2half2(p45);

        half2 fa = __hmul2(a0, sAfa[lane]);
        half2 fb = __hmul2(a0, sAfb[lane]);
        half2 sa = __hmul2(a0, sAsa[lane]);
        half2 sb = __hmul2(a0, sAsb[lane]);
        fa = __hfma2(a1, sAfa[32 + lane], fa);  fb = __hfma2(a1, sAfb[32 + lane], fb);
        sa = __hfma2(a1, sAsa[32 + lane], sa);  sb = __hfma2(a1, sAsb[32 + lane], sb);
        fa = __hfma2(a2, sAfa[64 + lane], fa);  fb = __hfma2(a2, sAfb[64 + lane], fb);
        sa = __hfma2(a2, sAsa[64 + lane], sa);  sb = __hfma2(a2, sAsb[64 + lane], sb);
        fa = __hfma2(a3, sAfa[96 + lane], fa);  fb = __hfma2(a3, sAfb[96 + lane], fb);
        sa = __hfma2(a3, sAsa[96 + lane], sa);  sb = __hfma2(a3, sAsb[96 + lane], sb);
        fa = __hfma2(a4, sAfa[128 + lane], fa); fb = __hfma2(a4, sAfb[128 + lane], fb);
        sa = __hfma2(a4, sAsa[128 + lane], sa); sb = __hfma2(a4, sAsb[128 + lane], sb);
        fa = __hfma2(a5, sAfa[160 + lane], fa); fb = __hfma2(a5, sAfb[160 + lane], fb);
        sa = __hfma2(a5, sAsa[160 + lane], sa); sb = __hfma2(a5, sAsb[160 + lane], sb);

        // add j-side halves (tj: x=hf01 y=hf23 z=hs01 w=hs23)
        fa = __hadd2(fa, *(half2*)&tj.x);
        fb = __hadd2(fb, *(half2*)&tj.y);
        sa = __hadd2(sa, *(half2*)&tj.z);
        sb = __hadd2(sb, *(half2*)&tj.w);

        // gate: fully half2
        half2 t0 = h2tanh_(__hadd2(fa, fi2a));
        half2 t1 = h2tanh_(__hadd2(fb, fi2b));

        // softplus: f32 spine
        float2 s01 = __half22float2(sa);
        float2 s23 = __half22float2(sb);
        float sp0 = sp2f(si.x + s01.x);
        float sp1 = sp2f(si.y + s01.y);
        float sp2 = sp2f(si.z + s23.x);
        float sp3 = sp2f(si.w + s23.y);
        half2 sp01 = __floats2half2_rn(sp0, sp1);
        half2 sp23 = __floats2half2_rn(sp2, sp3);

        // msg/(0.5*ln2) = (1+tanh)*sp2 ; max is monotone under the positive constant
        half2 m0 = __hfma2(t0, sp01, sp01);
        half2 m1 = __hfma2(t1, sp23, sp23);
        mx0 = __hmax2(mx0, m0);
        mx1 = __hmax2(mx1, m1);
    }

    float2 mf0 = __half22float2(mx0);
    float2 mf1 = __half22float2(mx1);

    float4 g4 = ((const float4*)(gamma + (size_t)l * CC))[lane];
    float4 b4 = ((const float4*)(beta + (size_t)l * CC))[lane];
    float4 m4 = ((const float4*)(bmean + (size_t)l * CC))[lane];
    float4 v4 = ((const float4*)(bvar + (size_t)l * CC))[lane];
    float4* H4 = (float4*)g_h;
    float4 h4 = H4[(size_t)n * 32 + lane];
    h4.x += (mf0.x * MSCALE - m4.x) * rsqrtf(v4.x + 1e-5f) * g4.x + b4.x;
    h4.y += (mf0.y * MSCALE - m4.y) * rsqrtf(v4.y + 1e-5f) * g4.y + b4.y;
    h4.z += (mf1.x * MSCALE - m4.z) * rsqrtf(v4.z + 1e-5f) * g4.z + b4.z;
    h4.w += (mf1.y * MSCALE - m4.w) * rsqrtf(v4.w + 1e-5f) * g4.w + b4.w;
    H4[(size_t)n * 32 + lane] = h4;
}

// ---------------- final head + h copy ----------------
__global__ void __launch_bounds__(256) k_final(const float* __restrict__ linW,
                                               const float* __restrict__ linb,
                                               float* __restrict__ out) {
    int tid = threadIdx.x;
    int lane = tid & 31;
    int n = (blockIdx.x * 256 + tid) >> 5;
    if (n >= NN) return;
    float4 h4 = ((const float4*)g_h)[(size_t)n * 32 + lane];
#pragma unroll
    for (int j = 0; j < KK; j++) {
        float4 w = ((const float4*)linW)[j * 32 + lane];
        float p = h4.x * w.x + h4.y * w.y + h4.z * w.z + h4.w * w.w;
#pragma unroll
        for (int d = 16; d; d >>= 1) p += __shfl_xor_sync(0xffffffffu, p, d);
        if (lane == 0) out[(size_t)n * KK + j] = p + __ldg(linb + j);
    }
    ((float4*)(out + (size_t)NN * KK))[(size_t)n * 32 + lane] = h4;
}

// ---------------- launch ----------------
extern "C" void kernel_launch(void* const* d_in, const int* in_sizes, int n_in,
                              void* d_out, int out_size) {
    const float* x       = (const float*)d_in[0];
    const int*   ei      = (const int*)d_in[1];
    const float* ea      = (const float*)d_in[2];
    const float* node_W  = (const float*)d_in[3];
    const float* node_b  = (const float*)d_in[4];
    const float* edge_W  = (const float*)d_in[5];
    const float* edge_b  = (const float*)d_in[6];
    const float* Wf      = (const float*)d_in[7];
    const float* bf      = (const float*)d_in[8];
    const float* Ws      = (const float*)d_in[9];
    const float* bs      = (const float*)d_in[10];
    const float* gamma   = (const float*)d_in[11];
    const float* beta    = (const float*)d_in[12];
    const float* bn_mean = (const float*)d_in[13];
    const float* bn_var  = (const float*)d_in[14];
    const float* lin_W   = (const float*)d_in[15];
    const float* lin_b   = (const float*)d_in[16];
    float* out = (float*)d_out;

    cudaFuncSetAttribute(k_mma, cudaFuncAttributeMaxDynamicSharedMemorySize, SMEM_MMA);

    dim3 ggrid((NN + 127) / 128, 4);

    k_setup<<<ZB + FB + WB + NB, 256>>>(x, node_W, node_b, Wf, bf, Ws, bs,
                                        edge_W, edge_b);                        // 0
    k_hist<<<(EE + 255) / 256, 256>>>(ei);                                      // 1
    k_scan1<<<SC_NB, 256>>>();                                                  // 2
    k_scan2<<<1, 32>>>();                                                       // 3
    k_mma<<<ggrid, 256, SMEM_MMA>>>(0);                                         // 4
    k_scan3<<<SC_NB, 256>>>();                                                  // 5
    k_scatter<<<(EE + 255) / 256, 256>>>(ei, ea);                               // 6
    k_agg<<<(NN * 32 + 255) / 256, 256>>>(gamma, beta, bn_mean, bn_var, 0);     // 7

    for (int l = 1; l < LL; l++) {
        k_mma<<<ggrid, 256, SMEM_MMA>>>(l);
        k_agg<<<(NN * 32 + 255) / 256, 256>>>(gamma, beta, bn_mean, bn_var, l);
    }

    k_final<<<(NN * 32 + 255) / 256, 256>>>(lin_W, lin_b, out);
}

// round 8
// speedup vs baseline: 2.0898x; 1.0495x over previous
#include <cuda_runtime.h>
#include <cuda_fp16.h>
#include <cstdint>

#define NN 50000
#define EE 800000
#define CC 128
#define LL 3
#define KK 10

#define LOG2E 1.4426950408889634f
#define MSCALE 0.34657359027997264f  // 0.5 * ln2

// ---------------- scratch ----------------
__device__ __align__(16) float  g_h[NN * CC];                 // 25.6 MB
__device__ __align__(16) float  g_Ti[(size_t)NN * 256];       // [hf_i | hs_i] (prescaled)
__device__ __align__(16) __half g_Tj[(size_t)NN * 256];       // interleaved [hf_j x4 | hs_j x4]
__device__ __align__(16) float  g_Bcat[LL * 512 * CC];        // prescaled, pre-rounded tf32
__device__ __align__(16) float  g_AfT[LL * 6 * CC];           // x0.5
__device__ __align__(16) float  g_AsT[LL * 6 * CC];           // xlog2e
__device__ __align__(16) float  g_cf[LL * CC];
__device__ __align__(16) float  g_cs[LL * CC];
__device__ int   g_deg[NN + 1];
__device__ int   g_off[NN + 1];
__device__ int   g_cur[NN];
__device__ __align__(16) uint4 g_edge[EE];  // {src, ea01, ea23, ea45}
__device__ int   g_bsum[64];

// ---------------- math helpers ----------------
__device__ __forceinline__ float ex2f(float x) {
    float r; asm("ex2.approx.f32 %0, %1;" : "=f"(r) : "f"(x)); return r;
}
__device__ __forceinline__ float lg2f(float x) {
    float r; asm("lg2.approx.f32 %0, %1;" : "=f"(r) : "f"(x)); return r;
}
__device__ __forceinline__ half2 h2tanh_(half2 x) {
    uint32_t xi = *(uint32_t*)&x, ri;
    asm("tanh.approx.f16x2 %0, %1;" : "=r"(ri) : "r"(xi));
    return *(half2*)&ri;
}
__device__ __forceinline__ uint32_t f2tf32(float f) {
    uint32_t o; asm("cvt.rna.tf32.f32 %0, %1;" : "=r"(o) : "f"(f)); return o;
}
__device__ __forceinline__ void mma_tf32(float* d, const uint32_t* a, const uint32_t* b) {
    asm volatile(
        "mma.sync.aligned.m16n8k8.row.col.f32.tf32.tf32.f32 "
        "{%0,%1,%2,%3}, {%4,%5,%6,%7}, {%8,%9}, {%0,%1,%2,%3};"
        : "+f"(d[0]), "+f"(d[1]), "+f"(d[2]), "+f"(d[3])
        : "r"(a[0]), "r"(a[1]), "r"(a[2]), "r"(a[3]), "r"(b[0]), "r"(b[1]));
}
#define CP_COMMIT() asm volatile("cp.async.commit_group;")
#define CP_WAIT1()  asm volatile("cp.async.wait_group 1;")
#define CP_WAIT0()  asm volatile("cp.async.wait_group 0;")

// ---------------- fused setup: zero_deg | fold | bprep | node_encode ----------------
#define ZB 196
#define FB 21
#define WB 768
#define NB 25000
__global__ void k_setup(const float* __restrict__ x, const float* __restrict__ nW,
                        const float* __restrict__ nb,
                        const float* __restrict__ Wf, const float* __restrict__ bf,
                        const float* __restrict__ Ws, const float* __restrict__ bs,
                        const float* __restrict__ eW, const float* __restrict__ eb) {
    int b = blockIdx.x, tid = threadIdx.x;
    if (b < ZB) {
        int i = b * 256 + tid;
        if (i <= NN) g_deg[i] = 0;
    } else if (b < ZB + FB) {
        int t = (b - ZB) * 256 + tid;
        if (t >= LL * CC * 14) return;
        int l = t / (CC * 14);
        int r = t % (CC * 14);
        int c = r / 14, kk = r % 14;
        const float* rf = Wf + ((size_t)(l * CC + c) * 3 * CC) + 2 * CC;
        const float* rs = Ws + ((size_t)(l * CC + c) * 3 * CC) + 2 * CC;
        if (kk < 6) {
            float s = 0.f;
            for (int j = 0; j < CC; j++) s = fmaf(rf[j], eW[j * 6 + kk], s);
            g_AfT[l * 6 * CC + kk * CC + c] = s * 0.5f;
        } else if (kk < 12) {
            int k = kk - 6;
            float s = 0.f;
            for (int j = 0; j < CC; j++) s = fmaf(rs[j], eW[j * 6 + k], s);
            g_AsT[l * 6 * CC + k * CC + c] = s * LOG2E;
        } else if (kk == 12) {
            float s = bf[l * CC + c];
            for (int j = 0; j < CC; j++) s = fmaf(rf[j], eb[j], s);
            g_cf[l * CC + c] = s * 0.5f;
        } else {
            float s = bs[l * CC + c];
            for (int j = 0; j < CC; j++) s = fmaf(rs[j], eb[j], s);
            g_cs[l * CC + c] = s * LOG2E;
        }
    } else if (b < ZB + FB + WB) {
        int t = (b - ZB - FB) * 256 + tid;
        int l = t / (512 * CC);
        int r = t % (512 * CC);
        int n = r / CC, k = r % CC;
        int q = n >> 7, c = n & 127;
        const float* base = (q < 2 ? Wf : Ws);
        float scale = (q < 2) ? 0.5f : LOG2E;
        float v = base[(size_t)(l * CC + c) * 3 * CC + ((q & 1) ? CC : 0) + k] * scale;
        g_Bcat[t] = __uint_as_float(f2tf32(v));   // pre-round to tf32
    } else {
        int i = (b - ZB - FB - WB) * 256 + tid;
        int n = i / CC, c = i % CC;
        const float* xr = x + (size_t)n * 7;
        const float* wr = nW + (size_t)c * 7;
        float acc = nb[c];
#pragma unroll
        for (int k = 0; k < 7; k++) acc = fmaf(xr[k], wr[k], acc);
        g_h[i] = acc;
    }
}

// ---------------- CSR build (per-block int32/int64 self-detect) ----------------
__global__ void k_hist(const int* __restrict__ ei32) {
    int e = blockIdx.x * blockDim.x + threadIdx.x;
    int hi = (e < EE) ? ei32[2 * e + 1] : 0;
    int any32 = __syncthreads_or(hi != 0);
    if (e >= EE) return;
    int dst;
    if (any32) dst = ei32[EE + e];
    else       dst = (int)(((const long long*)ei32)[EE + e]);
    atomicAdd(&g_deg[dst], 1);
}

#define SC_NB 50
__global__ void __launch_bounds__(256) k_scan1() {
    __shared__ int sw[8];
    int b = blockIdx.x, tid = threadIdx.x, lane = tid & 31, wid = tid >> 5;
    int base = b * 1024 + tid * 4;
    int v[4];
    int run = 0;
#pragma unroll
    for (int i = 0; i < 4; i++) {
        int idx = base + i;
        int t = (idx <= NN) ? g_deg[idx] : 0;
        v[i] = run;
        run += t;
    }
    int incl = run;
#pragma unroll
    for (int d = 1; d < 32; d <<= 1) {
        int y = __shfl_up_sync(0xffffffffu, incl, d);
        if (lane >= d) incl += y;
    }
    if (lane == 31) sw[wid] = incl;
    __syncthreads();
    if (tid < 8) {
        int w = sw[tid];
        int wi = w;
#pragma unroll
        for (int d = 1; d < 8; d <<= 1) {
            int y = __shfl_up_sync(0xffu, wi, d);
            if (tid >= d) wi += y;
        }
        sw[tid] = wi - w;
        if (tid == 7) g_bsum[b] = wi;
    }
    __syncthreads();
    int off0 = sw[wid] + (incl - run);
#pragma unroll
    for (int i = 0; i < 4; i++) {
        int idx = base + i;
        if (idx <= NN) g_off[idx] = off0 + v[i];
    }
}

// adds prefix of block sums (computed locally) and fills g_cur
__global__ void __launch_bounds__(256) k_scan3() {
    __shared__ int wsum[2];
    int b = blockIdx.x, tid = threadIdx.x;
    if (tid < 64) {
        int v = (tid < b) ? g_bsum[tid] : 0;   // b <= 49 < 64
#pragma unroll
        for (int d = 16; d; d >>= 1) v += __shfl_xor_sync(0xffffffffu, v, d);
        if ((tid & 31) == 0) wsum[tid >> 5] = v;
    }
    __syncthreads();
    int add = wsum[0] + wsum[1];
#pragma unroll
    for (int i = 0; i < 4; i++) {
        int idx = b * 1024 + tid * 4 + i;
        if (idx <= NN) {
            int o = g_off[idx] + add;
            g_off[idx] = o;
            if (idx < NN) g_cur[idx] = o;
        }
    }
}

__global__ void k_scatter(const int* __restrict__ ei32, const float* __restrict__ ea) {
    int e = blockIdx.x * blockDim.x + threadIdx.x;
    int hi = (e < EE) ? ei32[2 * e + 1] : 0;
    int any32 = __syncthreads_or(hi != 0);
    if (e >= EE) return;
    int src, dst;
    if (any32) {
        src = ei32[e];
        dst = ei32[EE + e];
    } else {
        const long long* ll = (const long long*)ei32;
        src = (int)ll[e];
        dst = (int)ll[EE + e];
    }
    int pos = atomicAdd(&g_cur[dst], 1);
    const float* a = ea + (size_t)e * 6;
    half2 x01 = __floats2half2_rn(a[0], a[1]);
    half2 x23 = __floats2half2_rn(a[2], a[3]);
    half2 x45 = __floats2half2_rn(a[4], a[5]);
    uint4 u;
    u.x = (uint32_t)src;
    u.y = *(uint32_t*)&x01;
    u.z = *(uint32_t*)&x23;
    u.w = *(uint32_t*)&x45;
    g_edge[pos] = u;
}

// ---------------- mma.sync tf32 GEMM: T = h @ Bcat^T (M=NN, N=512, K=128) ----------------
// One CTA: 128 M-rows, all 4 N-tiles (A loaded once, B double-buffered via cp.async).
#define LDA 132
#define SMEM_MMA (3 * 128 * LDA * 4)

__device__ __forceinline__ void issue_b(const float* __restrict__ Bsrc, uint32_t* sBuf, int tid) {
#pragma unroll
    for (int i = 0; i < 16; i++) {
        int idx = tid + i * 256;
        int row = idx >> 5, col = (idx & 31) << 2;
        uint32_t sa = (uint32_t)__cvta_generic_to_shared(sBuf + row * LDA + col);
        asm volatile("cp.async.ca.shared.global [%0], [%1], 16;"
                     :: "r"(sa), "l"(Bsrc + (size_t)row * CC + col));
    }
    CP_COMMIT();
}

__device__ __forceinline__ void mma_compute(const uint32_t* sA, const uint32_t* sB,
                                            float acc[2][8][4],
                                            int wm, int wn, int gr, int tg) {
#pragma unroll
    for (int mi = 0; mi < 2; mi++)
#pragma unroll
        for (int ni = 0; ni < 8; ni++)
#pragma unroll
            for (int p = 0; p < 4; p++) acc[mi][ni][p] = 0.f;
#pragma unroll
    for (int ks = 0; ks < 16; ks++) {
        const int k0 = ks * 8;
        uint32_t a[2][4];
#pragma unroll
        for (int mi = 0; mi < 2; mi++) {
            const uint32_t* ap = sA + (wm + mi * 16 + gr) * LDA + k0 + tg;
            a[mi][0] = ap[0];
            a[mi][1] = ap[8 * LDA];
            a[mi][2] = ap[4];
            a[mi][3] = ap[8 * LDA + 4];
        }
        uint32_t b[8][2];
#pragma unroll
        for (int ni = 0; ni < 8; ni++) {
            const uint32_t* bp = sB + (wn + ni * 8 + gr) * LDA + k0 + tg;
            b[ni][0] = bp[0];
            b[ni][1] = bp[4];
        }
#pragma unroll
        for (int mi = 0; mi < 2; mi++)
#pragma unroll
            for (int ni = 0; ni < 8; ni++)
                mma_tf32(acc[mi][ni], a[mi], b[ni]);
    }
}

__device__ __forceinline__ void mma_epi(float acc[2][8][4], int q,
                                        int bm, int wm, int wn, int gr, int tg) {
    if ((q & 1) == 0) {
        const int cb = (q >> 1) * 128;
#pragma unroll
        for (int mi = 0; mi < 2; mi++) {
            int r0 = bm + wm + mi * 16 + gr;
            int r1 = r0 + 8;
#pragma unroll
            for (int ni = 0; ni < 8; ni++) {
                int lc = wn + ni * 8 + tg * 2;
                if (r0 < NN) *(float2*)(g_Ti + (size_t)r0 * 256 + cb + lc) = make_float2(acc[mi][ni][0], acc[mi][ni][1]);
                if (r1 < NN) *(float2*)(g_Ti + (size_t)r1 * 256 + cb + lc) = make_float2(acc[mi][ni][2], acc[mi][ni][3]);
            }
        }
    } else {
        const int add = (q == 3) ? 4 : 0;
#pragma unroll
        for (int mi = 0; mi < 2; mi++) {
            int r0 = bm + wm + mi * 16 + gr;
            int r1 = r0 + 8;
#pragma unroll
            for (int ni = 0; ni < 8; ni++) {
                int lc = wn + ni * 8 + tg * 2;
                int i0 = ((lc >> 2) << 3) + (lc & 3) + add;
                if (r0 < NN) *(__half2*)(g_Tj + (size_t)r0 * 256 + i0) = __floats2half2_rn(acc[mi][ni][0], acc[mi][ni][1]);
                if (r1 < NN) *(__half2*)(g_Tj + (size_t)r1 * 256 + i0) = __floats2half2_rn(acc[mi][ni][2], acc[mi][ni][3]);
            }
        }
    }
}

__global__ void __launch_bounds__(256) k_mma(int l) {
    extern __shared__ uint32_t smem_u[];
    uint32_t* sA = smem_u;
    uint32_t* sB0 = smem_u + 128 * LDA;
    uint32_t* sB1 = smem_u + 2 * 128 * LDA;
    const int tid = threadIdx.x;
    const int wid = tid >> 5, lane = tid & 31;
    const int bm = blockIdx.x * 128;
    const int wm = (wid >> 1) * 32, wn = (wid & 1) * 64;
    const int gr = lane >> 2, tg = lane & 3;

    const float* Bl = g_Bcat + (size_t)l * 512 * CC;
    issue_b(Bl + 0 * 128 * CC, sB0, tid);
    issue_b(Bl + 1 * 128 * CC, sB1, tid);

    // A load + tf32 convert (once)
#pragma unroll
    for (int i = 0; i < 16; i++) {
        int idx = tid + i * 256;
        int row = idx >> 5;
        int col = (idx & 31) << 2;
        float4 v = make_float4(0.f, 0.f, 0.f, 0.f);
        if (bm + row < NN) v = *(const float4*)(g_h + (size_t)(bm + row) * CC + col);
        uint32_t* d = sA + row * LDA + col;
        d[0] = f2tf32(v.x); d[1] = f2tf32(v.y); d[2] = f2tf32(v.z); d[3] = f2tf32(v.w);
    }

    float acc[2][8][4];

    CP_WAIT1(); __syncthreads();
    mma_compute(sA, sB0, acc, wm, wn, gr, tg);
    mma_epi(acc, 0, bm, wm, wn, gr, tg);
    __syncthreads();
    issue_b(Bl + 2 * 128 * CC, sB0, tid);
    CP_WAIT1(); __syncthreads();
    mma_compute(sA, sB1, acc, wm, wn, gr, tg);
    mma_epi(acc, 1, bm, wm, wn, gr, tg);
    __syncthreads();
    issue_b(Bl + 3 * 128 * CC, sB1, tid);
    CP_WAIT1(); __syncthreads();
    mma_compute(sA, sB0, acc, wm, wn, gr, tg);
    mma_epi(acc, 2, bm, wm, wn, gr, tg);
    __syncthreads();
    CP_WAIT0(); __syncthreads();
    mma_compute(sA, sB1, acc, wm, wn, gr, tg);
    mma_epi(acc, 3, bm, wm, wn, gr, tg);
}

// ---------------- per-layer aggregation + BN + residual (+ fused head on last) ----------------
__global__ void __launch_bounds__(256) k_agg(const float* __restrict__ gamma,
                                             const float* __restrict__ beta,
                                             const float* __restrict__ bmean,
                                             const float* __restrict__ bvar,
                                             int l, int last,
                                             const float* __restrict__ linW,
                                             const float* __restrict__ linb,
                                             float* __restrict__ out) {
    __shared__ half2 sAfa[192], sAfb[192], sAsa[192], sAsb[192];
    __shared__ float4 sC[64];
    int tid = threadIdx.x;
    if (tid < 192) {
        int k = tid >> 5, ln = tid & 31;
        const float* Af = g_AfT + (size_t)l * 6 * CC + k * CC + 4 * ln;
        const float* As_ = g_AsT + (size_t)l * 6 * CC + k * CC + 4 * ln;
        sAfa[tid] = __floats2half2_rn(Af[0], Af[1]);
        sAfb[tid] = __floats2half2_rn(Af[2], Af[3]);
        sAsa[tid] = __floats2half2_rn(As_[0], As_[1]);
        sAsb[tid] = __floats2half2_rn(As_[2], As_[3]);
    }
    if (tid < 32)
        sC[tid] = ((const float4*)(g_cf + (size_t)l * CC))[tid];
    else if (tid < 64)
        sC[tid] = ((const float4*)(g_cs + (size_t)l * CC))[tid - 32];
    __syncthreads();

    int lane = tid & 31;
    int n = (blockIdx.x * 256 + tid) >> 5;
    if (n >= NN) return;

    const float4* Ti4 = (const float4*)g_Ti;
    float4 fi = Ti4[(size_t)n * 64 + lane];        // hf_i (x0.5)
    float4 si = Ti4[(size_t)n * 64 + 32 + lane];   // hs_i (xlog2e)
    float4 c0 = sC[lane], c1 = sC[32 + lane];
    fi.x += c0.x; fi.y += c0.y; fi.z += c0.z; fi.w += c0.w;
    si.x += c1.x; si.y += c1.y; si.z += c1.z; si.w += c1.w;
    half2 fi2a = __floats2half2_rn(fi.x, fi.y);
    half2 fi2b = __floats2half2_rn(fi.z, fi.w);

    const uint4* Tj4 = (const uint4*)g_Tj;

    half2 mx0 = __floats2half2_rn(0.f, 0.f);
    half2 mx1 = mx0;
    int beg = g_off[n], end = g_off[n + 1];

    uint4 e0, e1, tj0;
    if (beg < end) {
        e0 = g_edge[beg];
        tj0 = Tj4[(size_t)e0.x * 32 + lane];
    }
    if (beg + 1 < end) e1 = g_edge[beg + 1];

    for (int j = beg; j < end; j++) {
        uint4 ec = e0;
        uint4 tj = tj0;
        if (j + 1 < end) {
            tj0 = Tj4[(size_t)e1.x * 32 + lane];
            e0 = e1;
        }
        if (j + 2 < end) e1 = g_edge[j + 2];

        half2 p01 = *(half2*)&ec.y;
        half2 p23 = *(half2*)&ec.z;
        half2 p45 = *(half2*)&ec.w;
        half2 a0 = __low2half2(p01), a1 = __high2half2(p01);
        half2 a2 = __low2half2(p23), a3 = __high2half2(p23);
        half2 a4 = __low2half2(p45), a5 = __high2half2(p45);

        half2 fa = __hmul2(a0, sAfa[lane]);
        half2 fb = __hmul2(a0, sAfb[lane]);
        half2 sa = __hmul2(a0, sAsa[lane]);
        half2 sb = __hmul2(a0, sAsb[lane]);
        fa = __hfma2(a1, sAfa[32 + lane], fa);  fb = __hfma2(a1, sAfb[32 + lane], fb);
        sa = __hfma2(a1, sAsa[32 + lane], sa);  sb = __hfma2(a1, sAsb[32 + lane], sb);
        fa = __hfma2(a2, sAfa[64 + lane], fa);  fb = __hfma2(a2, sAfb[64 + lane], fb);
        sa = __hfma2(a2, sAsa[64 + lane], sa);  sb = __hfma2(a2, sAsb[64 + lane], sb);
        fa = __hfma2(a3, sAfa[96 + lane], fa);  fb = __hfma2(a3, sAfb[96 + lane], fb);
        sa = __hfma2(a3, sAsa[96 + lane], sa);  sb = __hfma2(a3, sAsb[96 + lane], sb);
        fa = __hfma2(a4, sAfa[128 + lane], fa); fb = __hfma2(a4, sAfb[128 + lane], fb);
        sa = __hfma2(a4, sAsa[128 + lane], sa); sb = __hfma2(a4, sAsb[128 + lane], sb);
        fa = __hfma2(a5, sAfa[160 + lane], fa); fb = __hfma2(a5, sAfb[160 + lane], fb);
        sa = __hfma2(a5, sAsa[160 + lane], sa); sb = __hfma2(a5, sAsb[160 + lane], sb);

        fa = __hadd2(fa, *(half2*)&tj.x);
        fb = __hadd2(fb, *(half2*)&tj.y);
        sa = __hadd2(sa, *(half2*)&tj.z);
        sb = __hadd2(sb, *(half2*)&tj.w);

        // gate: half2
        half2 t0 = h2tanh_(__hadd2(fa, fi2a));
        half2 t1 = h2tanh_(__hadd2(fb, fi2b));

        // softplus/ln2 = log2(1 + 2^z'): no neg/abs/fmax needed in f32
        float2 s01 = __half22float2(sa);
        float2 s23 = __half22float2(sb);
        float u0 = ex2f(si.x + s01.x);
        float u1 = ex2f(si.y + s01.y);
        float u2 = ex2f(si.z + s23.x);
        float u3 = ex2f(si.w + s23.y);
        half2 sp01 = __floats2half2_rn(lg2f(1.f + u0), lg2f(1.f + u1));
        half2 sp23 = __floats2half2_rn(lg2f(1.f + u2), lg2f(1.f + u3));

        half2 m0 = __hfma2(t0, sp01, sp01);
        half2 m1 = __hfma2(t1, sp23, sp23);
        mx0 = __hmax2(mx0, m0);
        mx1 = __hmax2(mx1, m1);
    }

    float2 mf0 = __half22float2(mx0);
    float2 mf1 = __half22float2(mx1);

    float4 g4 = ((const float4*)(gamma + (size_t)l * CC))[lane];
    float4 b4 = ((const float4*)(beta + (size_t)l * CC))[lane];
    float4 m4 = ((const float4*)(bmean + (size_t)l * CC))[lane];
    float4 v4 = ((const float4*)(bvar + (size_t)l * CC))[lane];
    float4* H4 = (float4*)g_h;
    float4 h4 = H4[(size_t)n * 32 + lane];
    h4.x += (mf0.x * MSCALE - m4.x) * rsqrtf(v4.x + 1e-5f) * g4.x + b4.x;
    h4.y += (mf0.y * MSCALE - m4.y) * rsqrtf(v4.y + 1e-5f) * g4.y + b4.y;
    h4.z += (mf1.x * MSCALE - m4.z) * rsqrtf(v4.z + 1e-5f) * g4.z + b4.z;
    h4.w += (mf1.y * MSCALE - m4.w) * rsqrtf(v4.w + 1e-5f) * g4.w + b4.w;

    if (!last) {
        H4[(size_t)n * 32 + lane] = h4;
    } else {
        ((float4*)(out + (size_t)NN * KK))[(size_t)n * 32 + lane] = h4;
#pragma unroll
        for (int jq = 0; jq < KK; jq++) {
            float4 w = ((const float4*)linW)[jq * 32 + lane];
            float p = h4.x * w.x + h4.y * w.y + h4.z * w.z + h4.w * w.w;
#pragma unroll
            for (int d = 16; d; d >>= 1) p += __shfl_xor_sync(0xffffffffu, p, d);
            if (lane == 0) out[(size_t)n * KK + jq] = p + __ldg(linb + jq);
        }
    }
}

// ---------------- launch ----------------
extern "C" void kernel_launch(void* const* d_in, const int* in_sizes, int n_in,
                              void* d_out, int out_size) {
    const float* x       = (const float*)d_in[0];
    const int*   ei      = (const int*)d_in[1];
    const float* ea      = (const float*)d_in[2];
    const float* node_W  = (const float*)d_in[3];
    const float* node_b  = (const float*)d_in[4];
    const float* edge_W  = (const float*)d_in[5];
    const float* edge_b  = (const float*)d_in[6];
    const float* Wf      = (const float*)d_in[7];
    const float* bf      = (const float*)d_in[8];
    const float* Ws      = (const float*)d_in[9];
    const float* bs      = (const float*)d_in[10];
    const float* gamma   = (const float*)d_in[11];
    const float* beta    = (const float*)d_in[12];
    const float* bn_mean = (const float*)d_in[13];
    const float* bn_var  = (const float*)d_in[14];
    const float* lin_W   = (const float*)d_in[15];
    const float* lin_b   = (const float*)d_in[16];
    float* out = (float*)d_out;

    cudaFuncSetAttribute(k_mma, cudaFuncAttributeMaxDynamicSharedMemorySize, SMEM_MMA);

    int mgrid = (NN + 127) / 128;
    int agrid = (NN * 32 + 255) / 256;

    k_setup<<<ZB + FB + WB + NB, 256>>>(x, node_W, node_b, Wf, bf, Ws, bs,
                                        edge_W, edge_b);                          // 0
    k_hist<<<(EE + 255) / 256, 256>>>(ei);                                        // 1
    k_scan1<<<SC_NB, 256>>>();                                                    // 2
    k_mma<<<mgrid, 256, SMEM_MMA>>>(0);                                           // 3 (profiled)
    k_scan3<<<SC_NB, 256>>>();                                                    // 4
    k_scatter<<<(EE + 255) / 256, 256>>>(ei, ea);                                 // 5
    k_agg<<<agrid, 256>>>(gamma, beta, bn_mean, bn_var, 0, 0, lin_W, lin_b, out); // 6

    k_mma<<<mgrid, 256, SMEM_MMA>>>(1);
    k_agg<<<agrid, 256>>>(gamma, beta, bn_mean, bn_var, 1, 0, lin_W, lin_b, out);
    k_mma<<<mgrid, 256, SMEM_MMA>>>(2);
    k_agg<<<agrid, 256>>>(gamma, beta, bn_mean, bn_var, 2, 1, lin_W, lin_b, out);
}

// round 9
// speedup vs baseline: 2.1043x; 1.0069x over previous
#include <cuda_runtime.h>
#include <cuda_fp16.h>
#include <cstdint>

#define NN 50000
#define EE 800000
#define CC 128
#define LL 3
#define KK 10

#define LOG2E 1.4426950408889634f
#define MSCALE 0.34657359027997264f  // 0.5 * ln2

// ---------------- scratch ----------------
__device__ __align__(16) float  g_h[NN * CC];
__device__ __align__(16) float  g_Ti[(size_t)NN * 256];       // [hf_i | hs_i] (prescaled)
__device__ __align__(16) __half g_Tj[(size_t)NN * 256];       // interleaved [hf_j x4 | hs_j x4]
__device__ __align__(16) float  g_Bcat[LL * 512 * CC];        // prescaled, pre-rounded tf32
__device__ __align__(16) float  g_AfT[LL * 6 * CC];           // x0.5
__device__ __align__(16) float  g_AsT[LL * 6 * CC];           // xlog2e
__device__ __align__(16) float  g_cf[LL * CC];
__device__ __align__(16) float  g_cs[LL * CC];
__device__ int   g_deg[NN + 1];
__device__ int   g_off[NN + 1];
__device__ int   g_cur[NN];
__device__ __align__(16) uint4 g_edge[EE];  // {src, ea01, ea23, ea45}
__device__ int   g_bsum[64];

// ---------------- math helpers ----------------
__device__ __forceinline__ float ex2f(float x) {
    float r; asm("ex2.approx.f32 %0, %1;" : "=f"(r) : "f"(x)); return r;
}
__device__ __forceinline__ float lg2f(float x) {
    float r; asm("lg2.approx.f32 %0, %1;" : "=f"(r) : "f"(x)); return r;
}
__device__ __forceinline__ half2 h2tanh_(half2 x) {
    uint32_t xi = *(uint32_t*)&x, ri;
    asm("tanh.approx.f16x2 %0, %1;" : "=r"(ri) : "r"(xi));
    return *(half2*)&ri;
}
__device__ __forceinline__ uint32_t f2tf32(float f) {
    uint32_t o; asm("cvt.rna.tf32.f32 %0, %1;" : "=r"(o) : "f"(f)); return o;
}
__device__ __forceinline__ void mma_tf32(float* d, const uint32_t* a, const uint32_t* b) {
    asm volatile(
        "mma.sync.aligned.m16n8k8.row.col.f32.tf32.tf32.f32 "
        "{%0,%1,%2,%3}, {%4,%5,%6,%7}, {%8,%9}, {%0,%1,%2,%3};"
        : "+f"(d[0]), "+f"(d[1]), "+f"(d[2]), "+f"(d[3])
        : "r"(a[0]), "r"(a[1]), "r"(a[2]), "r"(a[3]), "r"(b[0]), "r"(b[1]));
}
#define CP_COMMIT() asm volatile("cp.async.commit_group;")
#define CP_WAIT1()  asm volatile("cp.async.wait_group 1;")
#define CP_WAIT0()  asm volatile("cp.async.wait_group 0;")

// ---------------- zero degree (fork stream) ----------------
__global__ void k_zero() {
    int i = blockIdx.x * blockDim.x + threadIdx.x;
    if (i <= NN) g_deg[i] = 0;
}

// ---------------- fused setup: fold | bprep | node_encode ----------------
#define FB 21
#define WB 768
#define NB 25000
__global__ void k_setup(const float* __restrict__ x, const float* __restrict__ nW,
                        const float* __restrict__ nb,
                        const float* __restrict__ Wf, const float* __restrict__ bf,
                        const float* __restrict__ Ws, const float* __restrict__ bs,
                        const float* __restrict__ eW, const float* __restrict__ eb) {
    int b = blockIdx.x, tid = threadIdx.x;
    if (b < FB) {
        int t = b * 256 + tid;
        if (t >= LL * CC * 14) return;
        int l = t / (CC * 14);
        int r = t % (CC * 14);
        int c = r / 14, kk = r % 14;
        const float* rf = Wf + ((size_t)(l * CC + c) * 3 * CC) + 2 * CC;
        const float* rs = Ws + ((size_t)(l * CC + c) * 3 * CC) + 2 * CC;
        if (kk < 6) {
            float s = 0.f;
            for (int j = 0; j < CC; j++) s = fmaf(rf[j], eW[j * 6 + kk], s);
            g_AfT[l * 6 * CC + kk * CC + c] = s * 0.5f;
        } else if (kk < 12) {
            int k = kk - 6;
            float s = 0.f;
            for (int j = 0; j < CC; j++) s = fmaf(rs[j], eW[j * 6 + k], s);
            g_AsT[l * 6 * CC + k * CC + c] = s * LOG2E;
        } else if (kk == 12) {
            float s = bf[l * CC + c];
            for (int j = 0; j < CC; j++) s = fmaf(rf[j], eb[j], s);
            g_cf[l * CC + c] = s * 0.5f;
        } else {
            float s = bs[l * CC + c];
            for (int j = 0; j < CC; j++) s = fmaf(rs[j], eb[j], s);
            g_cs[l * CC + c] = s * LOG2E;
        }
    } else if (b < FB + WB) {
        int t = (b - FB) * 256 + tid;
        int l = t / (512 * CC);
        int r = t % (512 * CC);
        int n = r / CC, k = r % CC;
        int q = n >> 7, c = n & 127;
        const float* base = (q < 2 ? Wf : Ws);
        float scale = (q < 2) ? 0.5f : LOG2E;
        float v = base[(size_t)(l * CC + c) * 3 * CC + ((q & 1) ? CC : 0) + k] * scale;
        g_Bcat[t] = __uint_as_float(f2tf32(v));
    } else {
        int i = (b - FB - WB) * 256 + tid;
        int n = i / CC, c = i % CC;
        const float* xr = x + (size_t)n * 7;
        const float* wr = nW + (size_t)c * 7;
        float acc = nb[c];
#pragma unroll
        for (int k = 0; k < 7; k++) acc = fmaf(xr[k], wr[k], acc);
        g_h[i] = acc;
    }
}

// ---------------- CSR build (per-block int32/int64 self-detect) ----------------
__global__ void k_hist(const int* __restrict__ ei32) {
    int e = blockIdx.x * blockDim.x + threadIdx.x;
    int hi = (e < EE) ? ei32[2 * e + 1] : 0;
    int any32 = __syncthreads_or(hi != 0);
    if (e >= EE) return;
    int dst;
    if (any32) dst = ei32[EE + e];
    else       dst = (int)(((const long long*)ei32)[EE + e]);
    atomicAdd(&g_deg[dst], 1);
}

#define SC_NB 50
__global__ void __launch_bounds__(256) k_scan1() {
    __shared__ int sw[8];
    int b = blockIdx.x, tid = threadIdx.x, lane = tid & 31, wid = tid >> 5;
    int base = b * 1024 + tid * 4;
    int v[4];
    int run = 0;
#pragma unroll
    for (int i = 0; i < 4; i++) {
        int idx = base + i;
        int t = (idx <= NN) ? g_deg[idx] : 0;
        v[i] = run;
        run += t;
    }
    int incl = run;
#pragma unroll
    for (int d = 1; d < 32; d <<= 1) {
        int y = __shfl_up_sync(0xffffffffu, incl, d);
        if (lane >= d) incl += y;
    }
    if (lane == 31) sw[wid] = incl;
    __syncthreads();
    if (tid < 8) {
        int w = sw[tid];
        int wi = w;
#pragma unroll
        for (int d = 1; d < 8; d <<= 1) {
            int y = __shfl_up_sync(0xffu, wi, d);
            if (tid >= d) wi += y;
        }
        sw[tid] = wi - w;
        if (tid == 7) g_bsum[b] = wi;
    }
    __syncthreads();
    int off0 = sw[wid] + (incl - run);
#pragma unroll
    for (int i = 0; i < 4; i++) {
        int idx = base + i;
        if (idx <= NN) g_off[idx] = off0 + v[i];
    }
}

__global__ void __launch_bounds__(256) k_scan3() {
    __shared__ int wsum[2];
    int b = blockIdx.x, tid = threadIdx.x;
    if (tid < 64) {
        int v = (tid < b) ? g_bsum[tid] : 0;
#pragma unroll
        for (int d = 16; d; d >>= 1) v += __shfl_xor_sync(0xffffffffu, v, d);
        if ((tid & 31) == 0) wsum[tid >> 5] = v;
    }
    __syncthreads();
    int add = wsum[0] + wsum[1];
#pragma unroll
    for (int i = 0; i < 4; i++) {
        int idx = b * 1024 + tid * 4 + i;
        if (idx <= NN) {
            int o = g_off[idx] + add;
            g_off[idx] = o;
            if (idx < NN) g_cur[idx] = o;
        }
    }
}

__global__ void k_scatter(const int* __restrict__ ei32, const float* __restrict__ ea) {
    int e = blockIdx.x * blockDim.x + threadIdx.x;
    int hi = (e < EE) ? ei32[2 * e + 1] : 0;
    int any32 = __syncthreads_or(hi != 0);
    if (e >= EE) return;
    int src, dst;
    if (any32) {
        src = ei32[e];
        dst = ei32[EE + e];
    } else {
        const long long* ll = (const long long*)ei32;
        src = (int)ll[e];
        dst = (int)ll[EE + e];
    }
    int pos = atomicAdd(&g_cur[dst], 1);
    const float* a = ea + (size_t)e * 6;
    half2 x01 = __floats2half2_rn(a[0], a[1]);
    half2 x23 = __floats2half2_rn(a[2], a[3]);
    half2 x45 = __floats2half2_rn(a[4], a[5]);
    uint4 u;
    u.x = (uint32_t)src;
    u.y = *(uint32_t*)&x01;
    u.z = *(uint32_t*)&x23;
    u.w = *(uint32_t*)&x45;
    g_edge[pos] = u;
}

// ---------------- mma.sync tf32 GEMM: T = h @ Bcat^T (M=NN, N=512, K=128) ----------------
// 512 threads/CTA: 16 warps, 4x4 warp grid of 32x32 tiles. A loaded once; B double-buffered.
#define LDA 132
#define SMEM_MMA (3 * 128 * LDA * 4)

__device__ __forceinline__ void issue_b(const float* __restrict__ Bsrc, uint32_t* sBuf, int tid) {
#pragma unroll
    for (int i = 0; i < 8; i++) {
        int idx = tid + i * 512;
        int row = idx >> 5, col = (idx & 31) << 2;
        uint32_t sa = (uint32_t)__cvta_generic_to_shared(sBuf + row * LDA + col);
        asm volatile("cp.async.ca.shared.global [%0], [%1], 16;"
                     :: "r"(sa), "l"(Bsrc + (size_t)row * CC + col));
    }
    CP_COMMIT();
}

__device__ __forceinline__ void mma_compute(const uint32_t* sA, const uint32_t* sB,
                                            float acc[2][4][4],
                                            int wm, int wn, int gr, int tg) {
#pragma unroll
    for (int mi = 0; mi < 2; mi++)
#pragma unroll
        for (int ni = 0; ni < 4; ni++)
#pragma unroll
            for (int p = 0; p < 4; p++) acc[mi][ni][p] = 0.f;
#pragma unroll
    for (int ks = 0; ks < 16; ks++) {
        const int k0 = ks * 8;
        uint32_t a[2][4];
#pragma unroll
        for (int mi = 0; mi < 2; mi++) {
            const uint32_t* ap = sA + (wm + mi * 16 + gr) * LDA + k0 + tg;
            a[mi][0] = ap[0];
            a[mi][1] = ap[8 * LDA];
            a[mi][2] = ap[4];
            a[mi][3] = ap[8 * LDA + 4];
        }
        uint32_t b[4][2];
#pragma unroll
        for (int ni = 0; ni < 4; ni++) {
            const uint32_t* bp = sB + (wn + ni * 8 + gr) * LDA + k0 + tg;
            b[ni][0] = bp[0];
            b[ni][1] = bp[4];
        }
#pragma unroll
        for (int mi = 0; mi < 2; mi++)
#pragma unroll
            for (int ni = 0; ni < 4; ni++)
                mma_tf32(acc[mi][ni], a[mi], b[ni]);
    }
}

__device__ __forceinline__ void mma_epi(float acc[2][4][4], int q,
                                        int bm, int wm, int wn, int gr, int tg) {
    if ((q & 1) == 0) {
        const int cb = (q >> 1) * 128;
#pragma unroll
        for (int mi = 0; mi < 2; mi++) {
            int r0 = bm + wm + mi * 16 + gr;
            int r1 = r0 + 8;
#pragma unroll
            for (int ni = 0; ni < 4; ni++) {
                int lc = wn + ni * 8 + tg * 2;
                if (r0 < NN) *(float2*)(g_Ti + (size_t)r0 * 256 + cb + lc) = make_float2(acc[mi][ni][0], acc[mi][ni][1]);
                if (r1 < NN) *(float2*)(g_Ti + (size_t)r1 * 256 + cb + lc) = make_float2(acc[mi][ni][2], acc[mi][ni][3]);
            }
        }
    } else {
        const int add = (q == 3) ? 4 : 0;
#pragma unroll
        for (int mi = 0; mi < 2; mi++) {
            int r0 = bm + wm + mi * 16 + gr;
            int r1 = r0 + 8;
#pragma unroll
            for (int ni = 0; ni < 4; ni++) {
                int lc = wn + ni * 8 + tg * 2;
                int i0 = ((lc >> 2) << 3) + (lc & 3) + add;
                if (r0 < NN) *(__half2*)(g_Tj + (size_t)r0 * 256 + i0) = __floats2half2_rn(acc[mi][ni][0], acc[mi][ni][1]);
                if (r1 < NN) *(__half2*)(g_Tj + (size_t)r1 * 256 + i0) = __floats2half2_rn(acc[mi][ni][2], acc[mi][ni][3]);
            }
        }
    }
}

__global__ void __launch_bounds__(512) k_mma(int l) {
    extern __shared__ uint32_t smem_u[];
    uint32_t* sA = smem_u;
    uint32_t* sB0 = smem_u + 128 * LDA;
    uint32_t* sB1 = smem_u + 2 * 128 * LDA;
    const int tid = threadIdx.x;
    const int wid = tid >> 5, lane = tid & 31;
    const int bm = blockIdx.x * 128;
    const int wm = (wid >> 2) * 32, wn = (wid & 3) * 32;
    const int gr = lane >> 2, tg = lane & 3;

    const float* Bl = g_Bcat + (size_t)l * 512 * CC;
    issue_b(Bl + 0 * 128 * CC, sB0, tid);
    issue_b(Bl + 1 * 128 * CC, sB1, tid);

    // A load + tf32 convert (once)
#pragma unroll
    for (int i = 0; i < 8; i++) {
        int idx = tid + i * 512;
        int row = idx >> 5;
        int col = (idx & 31) << 2;
        float4 v = make_float4(0.f, 0.f, 0.f, 0.f);
        if (bm + row < NN) v = *(const float4*)(g_h + (size_t)(bm + row) * CC + col);
        uint32_t* d = sA + row * LDA + col;
        d[0] = f2tf32(v.x); d[1] = f2tf32(v.y); d[2] = f2tf32(v.z); d[3] = f2tf32(v.w);
    }

    float acc[2][4][4];

    CP_WAIT1(); __syncthreads();
    mma_compute(sA, sB0, acc, wm, wn, gr, tg);
    mma_epi(acc, 0, bm, wm, wn, gr, tg);
    __syncthreads();
    issue_b(Bl + 2 * 128 * CC, sB0, tid);
    CP_WAIT1(); __syncthreads();
    mma_compute(sA, sB1, acc, wm, wn, gr, tg);
    mma_epi(acc, 1, bm, wm, wn, gr, tg);
    __syncthreads();
    issue_b(Bl + 3 * 128 * CC, sB1, tid);
    CP_WAIT1(); __syncthreads();
    mma_compute(sA, sB0, acc, wm, wn, gr, tg);
    mma_epi(acc, 2, bm, wm, wn, gr, tg);
    __syncthreads();
    CP_WAIT0(); __syncthreads();
    mma_compute(sA, sB1, acc, wm, wn, gr, tg);
    mma_epi(acc, 3, bm, wm, wn, gr, tg);
}

// ---------------- per-layer aggregation + BN + residual (+ fused head on last) ----------------
__global__ void __launch_bounds__(256) k_agg(const float* __restrict__ gamma,
                                             const float* __restrict__ beta,
                                             const float* __restrict__ bmean,
                                             const float* __restrict__ bvar,
                                             int l, int last,
                                             const float* __restrict__ linW,
                                             const float* __restrict__ linb,
                                             float* __restrict__ out) {
    __shared__ half2 sAfa[192], sAfb[192], sAsa[192], sAsb[192];
    __shared__ float4 sC[64];
    int tid = threadIdx.x;
    if (tid < 192) {
        int k = tid >> 5, ln = tid & 31;
        const float* Af = g_AfT + (size_t)l * 6 * CC + k * CC + 4 * ln;
        const float* As_ = g_AsT + (size_t)l * 6 * CC + k * CC + 4 * ln;
        sAfa[tid] = __floats2half2_rn(Af[0], Af[1]);
        sAfb[tid] = __floats2half2_rn(Af[2], Af[3]);
        sAsa[tid] = __floats2half2_rn(As_[0], As_[1]);
        sAsb[tid] = __floats2half2_rn(As_[2], As_[3]);
    }
    if (tid < 32)
        sC[tid] = ((const float4*)(g_cf + (size_t)l * CC))[tid];
    else if (tid < 64)
        sC[tid] = ((const float4*)(g_cs + (size_t)l * CC))[tid - 32];
    __syncthreads();

    int lane = tid & 31;
    int n = (blockIdx.x * 256 + tid) >> 5;
    if (n >= NN) return;

    const float4* Ti4 = (const float4*)g_Ti;
    float4 fi = Ti4[(size_t)n * 64 + lane];
    float4 si = Ti4[(size_t)n * 64 + 32 + lane];
    float4 c0 = sC[lane], c1 = sC[32 + lane];
    fi.x += c0.x; fi.y += c0.y; fi.z += c0.z; fi.w += c0.w;
    si.x += c1.x; si.y += c1.y; si.z += c1.z; si.w += c1.w;
    half2 fi2a = __floats2half2_rn(fi.x, fi.y);
    half2 fi2b = __floats2half2_rn(fi.z, fi.w);

    const uint4* Tj4 = (const uint4*)g_Tj;

    half2 mx0 = __floats2half2_rn(0.f, 0.f);
    half2 mx1 = mx0;
    int beg = g_off[n], end = g_off[n + 1];

    uint4 e0, e1, tj0;
    if (beg < end) {
        e0 = g_edge[beg];
        tj0 = Tj4[(size_t)e0.x * 32 + lane];
    }
    if (beg + 1 < end) e1 = g_edge[beg + 1];

    for (int j = beg; j < end; j++) {
        uint4 ec = e0;
        uint4 tj = tj0;
        if (j + 1 < end) {
            tj0 = Tj4[(size_t)e1.x * 32 + lane];
            e0 = e1;
        }
        if (j + 2 < end) e1 = g_edge[j + 2];

        half2 p01 = *(half2*)&ec.y;
        half2 p23 = *(half2*)&ec.z;
        half2 p45 = *(half2*)&ec.w;
        half2 a0 = __low2half2(p01), a1 = __high2half2(p01);
        half2 a2 = __low2half2(p23), a3 = __high2half2(p23);
        half2 a4 = __low2half2(p45), a5 = __high2half2(p45);

        half2 fa = __hmul2(a0, sAfa[lane]);
        half2 fb = __hmul2(a0, sAfb[lane]);
        half2 sa = __hmul2(a0, sAsa[lane]);
        half2 sb = __hmul2(a0, sAsb[lane]);
        fa = __hfma2(a1, sAfa[32 + lane], fa);  fb = __hfma2(a1, sAfb[32 + lane], fb);
        sa = __hfma2(a1, sAsa[32 + lane], sa);  sb = __hfma2(a1, sAsb[32 + lane], sb);
        fa = __hfma2(a2, sAfa[64 + lane], fa);  fb = __hfma2(a2, sAfb[64 + lane], fb);
        sa = __hfma2(a2, sAsa[64 + lane], sa);  sb = __hfma2(a2, sAsb[64 + lane], sb);
        fa = __hfma2(a3, sAfa[96 + lane], fa);  fb = __hfma2(a3, sAfb[96 + lane], fb);
        sa = __hfma2(a3, sAsa[96 + lane], sa);  sb = __hfma2(a3, sAsb[96 + lane], sb);
        fa = __hfma2(a4, sAfa[128 + lane], fa); fb = __hfma2(a4, sAfb[128 + lane], fb);
        sa = __hfma2(a4, sAsa[128 + lane], sa); sb = __hfma2(a4, sAsb[128 + lane], sb);
        fa = __hfma2(a5, sAfa[160 + lane], fa); fb = __hfma2(a5, sAfb[160 + lane], fb);
        sa = __hfma2(a5, sAsa[160 + lane], sa); sb = __hfma2(a5, sAsb[160 + lane], sb);

        fa = __hadd2(fa, *(half2*)&tj.x);
        fb = __hadd2(fb, *(half2*)&tj.y);
        sa = __hadd2(sa, *(half2*)&tj.z);
        sb = __hadd2(sb, *(half2*)&tj.w);

        half2 t0 = h2tanh_(__hadd2(fa, fi2a));
        half2 t1 = h2tanh_(__hadd2(fb, fi2b));

        float2 s01 = __half22float2(sa);
        float2 s23 = __half22float2(sb);
        float u0 = ex2f(si.x + s01.x);
        float u1 = ex2f(si.y + s01.y);
        float u2 = ex2f(si.z + s23.x);
        float u3 = ex2f(si.w + s23.y);
        half2 sp01 = __floats2half2_rn(lg2f(1.f + u0), lg2f(1.f + u1));
        half2 sp23 = __floats2half2_rn(lg2f(1.f + u2), lg2f(1.f + u3));

        half2 m0 = __hfma2(t0, sp01, sp01);
        half2 m1 = __hfma2(t1, sp23, sp23);
        mx0 = __hmax2(mx0, m0);
        mx1 = __hmax2(mx1, m1);
    }

    float2 mf0 = __half22float2(mx0);
    float2 mf1 = __half22float2(mx1);

    float4 g4 = ((const float4*)(gamma + (size_t)l * CC))[lane];
    float4 b4 = ((const float4*)(beta + (size_t)l * CC))[lane];
    float4 m4 = ((const float4*)(bmean + (size_t)l * CC))[lane];
    float4 v4 = ((const float4*)(bvar + (size_t)l * CC))[lane];
    float4* H4 = (float4*)g_h;
    float4 h4 = H4[(size_t)n * 32 + lane];
    h4.x += (mf0.x * MSCALE - m4.x) * rsqrtf(v4.x + 1e-5f) * g4.x + b4.x;
    h4.y += (mf0.y * MSCALE - m4.y) * rsqrtf(v4.y + 1e-5f) * g4.y + b4.y;
    h4.z += (mf1.x * MSCALE - m4.z) * rsqrtf(v4.z + 1e-5f) * g4.z + b4.z;
    h4.w += (mf1.y * MSCALE - m4.w) * rsqrtf(v4.w + 1e-5f) * g4.w + b4.w;

    if (!last) {
        H4[(size_t)n * 32 + lane] = h4;
    } else {
        ((float4*)(out + (size_t)NN * KK))[(size_t)n * 32 + lane] = h4;
#pragma unroll
        for (int jq = 0; jq < KK; jq++) {
            float4 w = ((const float4*)linW)[jq * 32 + lane];
            float p = h4.x * w.x + h4.y * w.y + h4.z * w.z + h4.w * w.w;
#pragma unroll
            for (int d = 16; d; d >>= 1) p += __shfl_xor_sync(0xffffffffu, p, d);
            if (lane == 0) out[(size_t)n * KK + jq] = p + __ldg(linb + jq);
        }
    }
}

// ---------------- launch ----------------
extern "C" void kernel_launch(void* const* d_in, const int* in_sizes, int n_in,
                              void* d_out, int out_size) {
    const float* x       = (const float*)d_in[0];
    const int*   ei      = (const int*)d_in[1];
    const float* ea      = (const float*)d_in[2];
    const float* node_W  = (const float*)d_in[3];
    const float* node_b  = (const float*)d_in[4];
    const float* edge_W  = (const float*)d_in[5];
    const float* edge_b  = (const float*)d_in[6];
    const float* Wf      = (const float*)d_in[7];
    const float* bf      = (const float*)d_in[8];
    const float* Ws      = (const float*)d_in[9];
    const float* bs      = (const float*)d_in[10];
    const float* gamma   = (const float*)d_in[11];
    const float* beta    = (const float*)d_in[12];
    const float* bn_mean = (const float*)d_in[13];
    const float* bn_var  = (const float*)d_in[14];
    const float* lin_W   = (const float*)d_in[15];
    const float* lin_b   = (const float*)d_in[16];
    float* out = (float*)d_out;

    cudaFuncSetAttribute(k_mma, cudaFuncAttributeMaxDynamicSharedMemorySize, SMEM_MMA);

    // fork stream + events (host objects; created per call, never destroyed —
    // kernel_launch only runs on the correctness and capture calls)
    cudaStream_t s2;
    cudaStreamCreateWithFlags(&s2, cudaStreamNonBlocking);
    cudaEvent_t evFork, evCSR;
    cudaEventCreateWithFlags(&evFork, cudaEventDisableTiming);
    cudaEventCreateWithFlags(&evCSR, cudaEventDisableTiming);

    int mgrid = (NN + 127) / 128;
    int agrid = (NN * 32 + 255) / 256;

    cudaEventRecord(evFork, 0);
    cudaStreamWaitEvent(s2, evFork, 0);

    // CSR chain on s2 (independent of setup/mma)
    k_zero<<<196, 256, 0, s2>>>();                                   // 0
    k_hist<<<(EE + 255) / 256, 256, 0, s2>>>(ei);                    // 1
    // main chain
    k_setup<<<FB + WB + NB, 256>>>(x, node_W, node_b, Wf, bf, Ws, bs,
                                   edge_W, edge_b);                  // 2
    k_mma<<<mgrid, 512, SMEM_MMA>>>(0);                              // 3 (profiled)
    // rest of CSR chain
    k_scan1<<<SC_NB, 256, 0, s2>>>();                                // 4
    k_scan3<<<SC_NB, 256, 0, s2>>>();                                // 5
    k_scatter<<<(EE + 255) / 256, 256, 0, s2>>>(ei, ea);             // 6
    cudaEventRecord(evCSR, s2);

    // join: agg(0) needs both mma(0) (main) and scatter (s2)
    cudaStreamWaitEvent(0, evCSR, 0);
    k_agg<<<agrid, 256>>>(gamma, beta, bn_mean, bn_var, 0, 0, lin_W, lin_b, out);

    k_mma<<<mgrid, 512, SMEM_MMA>>>(1);
    k_agg<<<agrid, 256>>>(gamma, beta, bn_mean, bn_var, 1, 0, lin_W, lin_b, out);
    k_mma<<<mgrid, 512, SMEM_MMA>>>(2);
    k_agg<<<agrid, 256>>>(gamma, beta, bn_mean, bn_var, 2, 1, lin_W, lin_b, out);
}